// round 10
// baseline (speedup 1.0000x reference)
#include <cuda_runtime.h>
#include <math.h>
#include <stdint.h>
#include <string.h>

// ---------------------------------------------------------------------------
// Problem constants
//   inputs [2048, 84, 84, 4] NHWC fp32
//   conv 3x3 s2 SAME x4 (ELU), channels 4->32->32->32->32
//   84 -> 42 -> 21 -> 11 -> 6   (FEAT = 6*6*32 = 1152)
//   LSTM size 256 over TL=64 steps, NT=32 trajectories, forget_bias=1
//   FC 256 -> 18
// ---------------------------------------------------------------------------

#define NIMG   2048
#define NT     32
#define TL     64
#define FEAT   1152
#define HID    256
#define NOUT   18

typedef unsigned long long u64;

// ---------------- packed f32x2 helpers (FFMA2: PTX-only pattern) -----------
__device__ __forceinline__ u64 pack2(float a, float b) {
    u64 d; asm("mov.b64 %0, {%1, %2};" : "=l"(d) : "f"(a), "f"(b)); return d;
}
__device__ __forceinline__ float2 unpack2(u64 v) {
    float2 r; asm("mov.b64 {%0, %1}, %2;" : "=f"(r.x), "=f"(r.y) : "l"(v)); return r;
}
__device__ __forceinline__ void fma2(u64& d, u64 a, u64 b) {
    asm("fma.rn.f32x2 %0, %1, %2, %0;" : "+l"(d) : "l"(a), "l"(b));
}
__device__ __forceinline__ float sum2(u64 v) {
    float2 r = unpack2(v); return r.x + r.y;
}

__device__ __forceinline__ float elu_(float v) { return v > 0.f ? v : (__expf(v) - 1.f); }

// ------------------------- device scratch (no cudaMalloc allowed) ----------
__device__ float g_c1[(size_t)NIMG * 42 * 42 * 32];   // 462 MB
__device__ float g_c2[(size_t)NIMG * 21 * 21 * 32];   // 116 MB
__device__ float g_c3[(size_t)NIMG * 11 * 11 * 32];   //  32 MB
__device__ float g_c4[(size_t)NIMG * 6 * 6 * 32];     //   9 MB
__device__ float g_xg[(size_t)NIMG * 1024];           //   8 MB  x@Wx + b
__device__ u64   g_whr2[128 * HID * 4];               //   1 MB  Wh k-paired

// ---------------------------------------------------------------------------
// Wh reorder (k-paired): whr2[(k2*256 + t)*4 + g] =
//   ( lstm_w[(1152+2*k2)*1024 + g*256 + t], lstm_w[(1152+2*k2+1)*1024 + g*256 + t] )
// ---------------------------------------------------------------------------
__global__ void reorder_wh2_k(const float* __restrict__ lw, u64* __restrict__ whr2)
{
    const int k2 = blockIdx.x;    // 0..127 (h input dim pair)
    const int t  = threadIdx.x;   // 0..255 (hidden index)
    const float* r0 = lw + (size_t)(FEAT + 2 * k2) * 1024;
    const float* r1 = lw + (size_t)(FEAT + 2 * k2 + 1) * 1024;
    u64* dst = whr2 + ((size_t)k2 * 256 + t) * 4;
    dst[0] = pack2(r0[t],       r1[t]);         // i
    dst[1] = pack2(r0[256 + t], r1[256 + t]);   // j
    dst[2] = pack2(r0[512 + t], r1[512 + t]);   // f
    dst[3] = pack2(r0[768 + t], r1[768 + t]);   // o
}

// ---------------------------------------------------------------------------
// conv1 v5: Cin=4 -> Cout=32, 84x84 -> 42x42, pad_begin=0.
// ci-pair f32x2: acc[co] = (even-ci sum, odd-ci sum). Input float4 is two
// natural ci-pairs (no broadcast movs). Weights pre-paired in smem.
// 352 threads = 8 cg x 11 oxt(TOX=4) x 4 rows; one image per block.
// ---------------------------------------------------------------------------
__global__ void __launch_bounds__(352, 2)
conv1_v5(const float* __restrict__ in, const float* __restrict__ w,
         const float* __restrict__ bias, float* __restrict__ out)
{
    __shared__ __align__(16) u64 sw2[9 * 2 * 32];     // [kpos][p][co] pairs
    const int tid = threadIdx.x;
    for (int i = tid; i < 9 * 2 * 32; i += 352) {
        const int kpos = i >> 6, p = (i >> 5) & 1, co = i & 31;
        sw2[i] = pack2(w[(kpos * 4 + 2 * p) * 32 + co],
                       w[(kpos * 4 + 2 * p + 1) * 32 + co]);
    }
    __syncthreads();

    const int cg   = tid & 7;
    const int rest = tid >> 3;
    const int oxg  = rest % 11;
    const int ry   = rest / 11;
    const int oy   = blockIdx.x * 4 + ry;
    const int n    = blockIdx.y;
    const int co0  = cg * 4;
    const int ox0  = oxg * 4;
    if (oy >= 42) return;

    u64 acc[4][4];
#pragma unroll
    for (int i = 0; i < 4; i++)
#pragma unroll
        for (int c = 0; c < 4; c++) acc[i][c] = 0ull;

#pragma unroll 1
    for (int ky = 0; ky < 3; ky++) {
        const int iy = oy * 2 + ky;
        if (iy >= 84) continue;
        const float* inr = in + ((size_t)(n * 84 + iy) * 84) * 4;
#pragma unroll
        for (int kx = 0; kx < 3; kx++) {
            const u64* swk = sw2 + (ky * 3 + kx) * 2 * 32;
            const ulonglong2 wa01 = *(const ulonglong2*)(swk + co0);
            const ulonglong2 wa23 = *(const ulonglong2*)(swk + co0 + 2);
            const ulonglong2 wb01 = *(const ulonglong2*)(swk + 32 + co0);
            const ulonglong2 wb23 = *(const ulonglong2*)(swk + 32 + co0 + 2);
#pragma unroll
            for (int i = 0; i < 4; i++) {
                const int ix = (ox0 + i) * 2 + kx;
                if (ix < 84) {
                    const ulonglong2 xv = *(const ulonglong2*)(inr + (size_t)ix * 4);
                    fma2(acc[i][0], xv.x, wa01.x);
                    fma2(acc[i][1], xv.x, wa01.y);
                    fma2(acc[i][2], xv.x, wa23.x);
                    fma2(acc[i][3], xv.x, wa23.y);
                    fma2(acc[i][0], xv.y, wb01.x);
                    fma2(acc[i][1], xv.y, wb01.y);
                    fma2(acc[i][2], xv.y, wb23.x);
                    fma2(acc[i][3], xv.y, wb23.y);
                }
            }
        }
    }
    const float4 bv = *(const float4*)(bias + co0);
    float* outr = out + ((size_t)(n * 42 + oy) * 42) * 32 + co0;
#pragma unroll
    for (int i = 0; i < 4; i++) {
        const int ox = ox0 + i;
        if (ox < 42) {
            float4 v;
            v.x = elu_(sum2(acc[i][0]) + bv.x);
            v.y = elu_(sum2(acc[i][1]) + bv.y);
            v.z = elu_(sum2(acc[i][2]) + bv.z);
            v.w = elu_(sum2(acc[i][3]) + bv.w);
            *(float4*)(outr + (size_t)ox * 32) = v;
        }
    }
}

// ---------------------------------------------------------------------------
// convN v5: Cin=32 -> Cout=32, ci-pair f32x2.
// Per (kpos, quad-ci): 4 LDS.128 weights (reused over TOX pixels) +
// per pixel 1 LDG.128 + 8 fma2 — zero broadcast movs.
// smem weights pre-paired: sw2[kpos][p=ci/2][co] = (w[2p][co], w[2p+1][co]).
// ---------------------------------------------------------------------------
template <int IH, int IW, int OH, int OW, int PAD, int TOX, int OXT, int ROWS,
          int IPB, int BLK>
__global__ void __launch_bounds__(8 * OXT * ROWS * IPB, BLK)
conv32_v5(const float* __restrict__ in, const float* __restrict__ w,
          const float* __restrict__ bias, float* __restrict__ out)
{
    __shared__ __align__(16) u64 sw2[9 * 16 * 32];    // 36 KB
    const int tid = threadIdx.x;
    const int NTH = 8 * OXT * ROWS * IPB;
    for (int i = tid; i < 9 * 16 * 32; i += NTH) {
        const int kpos = i >> 9, p = (i >> 5) & 15, co = i & 31;
        sw2[i] = pack2(w[(kpos * 32 + 2 * p) * 32 + co],
                       w[(kpos * 32 + 2 * p + 1) * 32 + co]);
    }
    __syncthreads();

    const int cg  = tid & 7;
    int rest      = tid >> 3;
    const int oxg = rest % OXT;  rest /= OXT;
    const int ry  = rest % ROWS;
    const int img = rest / ROWS;
    const int co0 = cg * 4;
    const int ox0 = oxg * TOX;
    const int oy  = blockIdx.x * ROWS + ry;
    const int n   = blockIdx.y * IPB + img;
    if (oy >= OH) return;

    u64 acc[TOX][4];
#pragma unroll
    for (int i = 0; i < TOX; i++)
#pragma unroll
        for (int c = 0; c < 4; c++) acc[i][c] = 0ull;

#pragma unroll 1
    for (int ky = 0; ky < 3; ky++) {
        const int iy = oy * 2 + ky - PAD;
        if (iy < 0 || iy >= IH) continue;
        const float* inr = in + ((size_t)(n * IH + iy) * IW) * 32;
#pragma unroll
        for (int kx = 0; kx < 3; kx++) {
            const u64* swk = sw2 + (ky * 3 + kx) * 16 * 32;
#pragma unroll
            for (int c4 = 0; c4 < 32; c4 += 4) {
                const int p0 = c4 >> 1;                 // even pair index
                const ulonglong2 wa01 = *(const ulonglong2*)(swk + p0 * 32 + co0);
                const ulonglong2 wa23 = *(const ulonglong2*)(swk + p0 * 32 + co0 + 2);
                const ulonglong2 wb01 = *(const ulonglong2*)(swk + (p0 + 1) * 32 + co0);
                const ulonglong2 wb23 = *(const ulonglong2*)(swk + (p0 + 1) * 32 + co0 + 2);
#pragma unroll
                for (int i = 0; i < TOX; i++) {
                    const int ix = (ox0 + i) * 2 + kx - PAD;
                    if (ix >= 0 && ix < IW) {
                        const ulonglong2 xv =
                            *(const ulonglong2*)(inr + (size_t)ix * 32 + c4);
                        fma2(acc[i][0], xv.x, wa01.x);
                        fma2(acc[i][1], xv.x, wa01.y);
                        fma2(acc[i][2], xv.x, wa23.x);
                        fma2(acc[i][3], xv.x, wa23.y);
                        fma2(acc[i][0], xv.y, wb01.x);
                        fma2(acc[i][1], xv.y, wb01.y);
                        fma2(acc[i][2], xv.y, wb23.x);
                        fma2(acc[i][3], xv.y, wb23.y);
                    }
                }
            }
        }
    }
    const float4 bv = *(const float4*)(bias + co0);
    float* outr = out + ((size_t)(n * OH + oy) * OW) * 32 + co0;
#pragma unroll
    for (int i = 0; i < TOX; i++) {
        if (ox0 + i < OW) {
            float4 v;
            v.x = elu_(sum2(acc[i][0]) + bv.x);
            v.y = elu_(sum2(acc[i][1]) + bv.y);
            v.z = elu_(sum2(acc[i][2]) + bv.z);
            v.w = elu_(sum2(acc[i][3]) + bv.w);
            *(float4*)(outr + (size_t)(ox0 + i) * 32) = v;
        }
    }
}

// ---------------------------------------------------------------------------
// SGEMM: xg[2048,1024] = c4[2048,1152] @ lstm_w[0:1152, 0:1024] + lstm_b
// 128x128x8 tiling, 256 threads, 8x8 micro-tile as f32x2 pairs over columns.
// ---------------------------------------------------------------------------
__device__ __forceinline__ u64 bcast2(float x) {
    u64 d; asm("mov.b64 %0, {%1, %1};" : "=l"(d) : "f"(x)); return d;
}

__global__ void __launch_bounds__(256, 2)
sgemm_xg_v2(const float* __restrict__ A, const float* __restrict__ B,
            const float* __restrict__ bias, float* __restrict__ C)
{
    __shared__ __align__(16) float As[8][128];
    __shared__ __align__(16) float Bs[8][128];
    const int bx  = blockIdx.x;   // 0..7   (N tiles)
    const int by  = blockIdx.y;   // 0..15  (M tiles)
    const int tid = threadIdx.x;
    const int tr  = (tid / 16) * 8;
    const int tc  = (tid % 16) * 8;

    u64 acc[8][4];
#pragma unroll
    for (int i = 0; i < 8; i++)
#pragma unroll
        for (int j = 0; j < 4; j++) acc[i][j] = 0ull;

    const int ar = tid >> 1,  ac = (tid & 1) * 4;
    const int br = tid >> 5,  bc = (tid & 31) * 4;
    const float* Aptr = A + (size_t)(by * 128 + ar) * FEAT + ac;
    const float* Bptr = B + (size_t)br * 1024 + bx * 128 + bc;

    for (int k0 = 0; k0 < FEAT; k0 += 8) {
        const float4 av = *(const float4*)(Aptr + k0);
        As[ac + 0][ar] = av.x; As[ac + 1][ar] = av.y;
        As[ac + 2][ar] = av.z; As[ac + 3][ar] = av.w;
        *(float4*)&Bs[br][bc] = *(const float4*)(Bptr + (size_t)k0 * 1024);
        __syncthreads();
#pragma unroll
        for (int kk = 0; kk < 8; kk++) {
            const float4 a0 = *(const float4*)&As[kk][tr];
            const float4 a1 = *(const float4*)&As[kk][tr + 4];
            const ulonglong2 b0 = *(const ulonglong2*)&Bs[kk][tc];
            const ulonglong2 b1 = *(const ulonglong2*)&Bs[kk][tc + 4];
            const float a[8] = {a0.x, a0.y, a0.z, a0.w, a1.x, a1.y, a1.z, a1.w};
#pragma unroll
            for (int i = 0; i < 8; i++) {
                const u64 ab = bcast2(a[i]);
                fma2(acc[i][0], ab, b0.x);
                fma2(acc[i][1], ab, b0.y);
                fma2(acc[i][2], ab, b1.x);
                fma2(acc[i][3], ab, b1.y);
            }
        }
        __syncthreads();
    }

#pragma unroll
    for (int i = 0; i < 8; i++) {
        const int row = by * 128 + tr + i;
        float* crow = C + (size_t)row * 1024 + bx * 128 + tc;
#pragma unroll
        for (int j = 0; j < 2; j++) {
            const float2 p0 = unpack2(acc[i][j * 2 + 0]);
            const float2 p1 = unpack2(acc[i][j * 2 + 1]);
            float4 v;
            v.x = p0.x + bias[bx * 128 + tc + j * 4 + 0];
            v.y = p0.y + bias[bx * 128 + tc + j * 4 + 1];
            v.z = p1.x + bias[bx * 128 + tc + j * 4 + 2];
            v.w = p1.y + bias[bx * 128 + tc + j * 4 + 3];
            *(float4*)(crow + j * 4) = v;
        }
    }
}

// ---------------------------------------------------------------------------
// Fused LSTM recurrence + FC, k-paired f32x2.
// Thread t owns c[t] and 4 gate accumulators, each an (even-k, odd-k) pair.
// Per k-pair: 1 LDS.64 (h pair, natural u64) + 2 LDG.128 (4 gate weight
// pairs) + 4 fma2 = 8 MACs, no movs. h lives in SMEM; FC head in warps 0..5.
// ---------------------------------------------------------------------------
__device__ __forceinline__ float sigmoidf_(float x) { return 1.f / (1.f + expf(-x)); }

__global__ void __launch_bounds__(256)
lstm_fused_v3(const float* __restrict__ xg, const u64* __restrict__ whr2,
              const float* __restrict__ fcw, const float* __restrict__ fcb,
              const float* __restrict__ c0, const float* __restrict__ h0,
              float* __restrict__ out)
{
    const int n   = blockIdx.x;    // trajectory
    const int tid = threadIdx.x;   // hidden index
    __shared__ __align__(16) float sh[HID];

    float c = c0[(size_t)n * HID + tid];
    sh[tid] = h0[(size_t)n * HID + tid];
    __syncthreads();

    const int wrp = tid >> 5, lane = tid & 31;

    for (int t = 0; t < TL; t++) {
        const float* xrow = xg + (size_t)(n * TL + t) * 1024;
        u64 ai = pack2(xrow[tid],       0.f);
        u64 aj = pack2(xrow[256 + tid], 0.f);
        u64 af = pack2(xrow[512 + tid], 0.f);
        u64 ao = pack2(xrow[768 + tid], 0.f);

#pragma unroll 4
        for (int k2 = 0; k2 < 128; k2++) {
            const u64 h2 = *(const u64*)(sh + 2 * k2);
            const ulonglong2* wp =
                (const ulonglong2*)(whr2 + ((size_t)k2 * 256 + tid) * 4);
            const ulonglong2 w01 = wp[0];   // (i, j) pairs
            const ulonglong2 w23 = wp[1];   // (f, o) pairs
            fma2(ai, h2, w01.x);
            fma2(aj, h2, w01.y);
            fma2(af, h2, w23.x);
            fma2(ao, h2, w23.y);
        }
        const float gi = sum2(ai), gj = sum2(aj);
        const float gf = sum2(af), go = sum2(ao);

        const float nc = c * sigmoidf_(gf + 1.f) + sigmoidf_(gi) * tanhf(gj);
        const float nh = tanhf(nc) * sigmoidf_(go);
        c = nc;

        __syncthreads();
        sh[tid] = nh;
        __syncthreads();

        // FC head: 18 columns, warps 0..5 take 3 columns each
        if (wrp < 6) {
#pragma unroll
            for (int cc = 0; cc < 3; cc++) {
                const int col = wrp * 3 + cc;
                float s = 0.f;
#pragma unroll
                for (int k = lane; k < HID; k += 32) s += sh[k] * fcw[(size_t)k * NOUT + col];
#pragma unroll
                for (int off = 16; off; off >>= 1) s += __shfl_down_sync(0xffffffffu, s, off);
                if (lane == 0)
                    out[(size_t)(n * TL + t) * NOUT + col] = s + fcb[col];
            }
        }
    }
}

// ---------------------------------------------------------------------------
// Launch
// ---------------------------------------------------------------------------
extern "C" void kernel_launch(void* const* d_in, const int* in_sizes, int n_in,
                              void* d_out, int out_size)
{
    (void)in_sizes; (void)n_in; (void)out_size;
    const float* inp = (const float*)d_in[0];
    const float* w1  = (const float*)d_in[1];
    const float* b1  = (const float*)d_in[2];
    const float* w2  = (const float*)d_in[3];
    const float* b2  = (const float*)d_in[4];
    const float* w3  = (const float*)d_in[5];
    const float* b3  = (const float*)d_in[6];
    const float* w4  = (const float*)d_in[7];
    const float* b4  = (const float*)d_in[8];
    const float* lw  = (const float*)d_in[9];
    const float* lb  = (const float*)d_in[10];
    const float* fw  = (const float*)d_in[11];
    const float* fb  = (const float*)d_in[12];
    const float* c0  = (const float*)d_in[13];
    const float* h0  = (const float*)d_in[14];
    float* out = (float*)d_out;

    float *c1, *c2, *c3, *c4, *xg;
    u64* whr2;
    cudaGetSymbolAddress((void**)&c1,   g_c1);
    cudaGetSymbolAddress((void**)&c2,   g_c2);
    cudaGetSymbolAddress((void**)&c3,   g_c3);
    cudaGetSymbolAddress((void**)&c4,   g_c4);
    cudaGetSymbolAddress((void**)&xg,   g_xg);
    cudaGetSymbolAddress((void**)&whr2, g_whr2);

    // Wh reorder (independent of conv chain)
    reorder_wh2_k<<<128, 256>>>(lw, whr2);

    // conv stack — ci-pair f32x2 inner loops (no broadcast movs).
    // conv1: 84->42, TOX=4, 352 thr (8cg x 11oxt x 4rows), grid (11, 2048)
    conv1_v5<<<dim3(11, NIMG), 352>>>(inp, w1, b1, c1);
    // conv2: 42->21, TOX=4 OXT=6 ROWS=4 IPB=1 BLK=3 -> 192 thr, grid (6, 2048)
    conv32_v5<42, 42, 21, 21, 0, 4, 6, 4, 1, 3><<<dim3(6, NIMG), 192>>>(c1, w2, b2, c2);
    // conv3: 21->11, TOX=4 OXT=3 ROWS=8 IPB=1 BLK=3 -> 192 thr, grid (2, 2048)
    conv32_v5<21, 21, 11, 11, 1, 4, 3, 8, 1, 3><<<dim3(2, NIMG), 192>>>(c2, w3, b3, c3);
    // conv4: 11->6,  TOX=3 OXT=2 ROWS=6 IPB=2 BLK=3 -> 192 thr, grid (1, 1024)
    conv32_v5<11, 11,  6,  6, 1, 3, 2, 6, 2, 3><<<dim3(1, NIMG / 2), 192>>>(c3, w4, b4, c4);

    // time-parallel part of the LSTM input GEMM (+ bias), f32x2 micro-kernel
    sgemm_xg_v2<<<dim3(8, 16), 256>>>(c4, lw, lb, xg);

    // recurrence + FC head fused, one persistent block per trajectory
    lstm_fused_v3<<<NT, HID>>>(xg, whr2, fw, fb, c0, h0, out);
}

// round 11
// speedup vs baseline: 1.0238x; 1.0238x over previous
#include <cuda_runtime.h>
#include <math.h>
#include <stdint.h>
#include <string.h>

// ---------------------------------------------------------------------------
// Problem constants
//   inputs [2048, 84, 84, 4] NHWC fp32
//   conv 3x3 s2 SAME x4 (ELU), channels 4->32->32->32->32
//   84 -> 42 -> 21 -> 11 -> 6   (FEAT = 6*6*32 = 1152)
//   LSTM size 256 over TL=64 steps, NT=32 trajectories, forget_bias=1
//   FC 256 -> 18
// ---------------------------------------------------------------------------

#define NIMG   2048
#define NT     32
#define TL     64
#define FEAT   1152
#define HID    256
#define NOUT   18

typedef unsigned long long u64;

// ---------------- packed f32x2 helpers (FFMA2: PTX-only pattern) -----------
__device__ __forceinline__ u64 pack2(float a, float b) {
    u64 d; asm("mov.b64 %0, {%1, %2};" : "=l"(d) : "f"(a), "f"(b)); return d;
}
__device__ __forceinline__ float2 unpack2(u64 v) {
    float2 r; asm("mov.b64 {%0, %1}, %2;" : "=f"(r.x), "=f"(r.y) : "l"(v)); return r;
}
__device__ __forceinline__ void fma2(u64& d, u64 a, u64 b) {
    asm("fma.rn.f32x2 %0, %1, %2, %0;" : "+l"(d) : "l"(a), "l"(b));
}
__device__ __forceinline__ float sum2(u64 v) {
    float2 r = unpack2(v); return r.x + r.y;
}
__device__ __forceinline__ u64 bcast2(float x) {
    u64 d; asm("mov.b64 %0, {%1, %1};" : "=l"(d) : "f"(x)); return d;
}

__device__ __forceinline__ float elu_(float v) { return v > 0.f ? v : (__expf(v) - 1.f); }

// ------------------------- device scratch (no cudaMalloc allowed) ----------
__device__ float g_c1[(size_t)NIMG * 42 * 42 * 32];   // 462 MB
__device__ float g_c2[(size_t)NIMG * 21 * 21 * 32];   // 116 MB
__device__ float g_c3[(size_t)NIMG * 11 * 11 * 32];   //  32 MB
__device__ float g_c4[(size_t)NIMG * 6 * 6 * 32];     //   9 MB
__device__ float g_xg[(size_t)NIMG * 1024];           //   8 MB  x@Wx + b
__device__ u64   g_whr2[128 * HID * 4];               //   1 MB  Wh k-paired

// ---------------------------------------------------------------------------
// Wh reorder (k-paired): whr2[(k2*256 + t)*4 + g] =
//   ( lstm_w[(1152+2*k2)*1024 + g*256 + t], lstm_w[(1152+2*k2+1)*1024 + g*256 + t] )
// ---------------------------------------------------------------------------
__global__ void reorder_wh2_k(const float* __restrict__ lw, u64* __restrict__ whr2)
{
    const int k2 = blockIdx.x;    // 0..127 (h input dim pair)
    const int t  = threadIdx.x;   // 0..255 (hidden index)
    const float* r0 = lw + (size_t)(FEAT + 2 * k2) * 1024;
    const float* r1 = lw + (size_t)(FEAT + 2 * k2 + 1) * 1024;
    u64* dst = whr2 + ((size_t)k2 * 256 + t) * 4;
    dst[0] = pack2(r0[t],       r1[t]);         // i
    dst[1] = pack2(r0[256 + t], r1[256 + t]);   // j
    dst[2] = pack2(r0[512 + t], r1[512 + t]);   // f
    dst[3] = pack2(r0[768 + t], r1[768 + t]);   // o
}

// ---------------------------------------------------------------------------
// conv1 v5: Cin=4 -> Cout=32, 84x84 -> 42x42, pad_begin=0.
// ci-pair f32x2: acc[co] = (even-ci sum, odd-ci sum). Input float4 is two
// natural ci-pairs (no broadcast movs). Weights pre-paired in smem.
// 352 threads = 8 cg x 11 oxt(TOX=4) x 4 rows; one image per block.
// ---------------------------------------------------------------------------
__global__ void __launch_bounds__(352, 2)
conv1_v5(const float* __restrict__ in, const float* __restrict__ w,
         const float* __restrict__ bias, float* __restrict__ out)
{
    __shared__ __align__(16) u64 sw2[9 * 2 * 32];     // [kpos][p][co] pairs
    const int tid = threadIdx.x;
    for (int i = tid; i < 9 * 2 * 32; i += 352) {
        const int kpos = i >> 6, p = (i >> 5) & 1, co = i & 31;
        sw2[i] = pack2(w[(kpos * 4 + 2 * p) * 32 + co],
                       w[(kpos * 4 + 2 * p + 1) * 32 + co]);
    }
    __syncthreads();

    const int cg   = tid & 7;
    const int rest = tid >> 3;
    const int oxg  = rest % 11;
    const int ry   = rest / 11;
    const int oy   = blockIdx.x * 4 + ry;
    const int n    = blockIdx.y;
    const int co0  = cg * 4;
    const int ox0  = oxg * 4;
    if (oy >= 42) return;

    u64 acc[4][4];
#pragma unroll
    for (int i = 0; i < 4; i++)
#pragma unroll
        for (int c = 0; c < 4; c++) acc[i][c] = 0ull;

#pragma unroll 1
    for (int ky = 0; ky < 3; ky++) {
        const int iy = oy * 2 + ky;
        if (iy >= 84) continue;
        const float* inr = in + ((size_t)(n * 84 + iy) * 84) * 4;
#pragma unroll
        for (int kx = 0; kx < 3; kx++) {
            const u64* swk = sw2 + (ky * 3 + kx) * 2 * 32;
            const ulonglong2 wa01 = *(const ulonglong2*)(swk + co0);
            const ulonglong2 wa23 = *(const ulonglong2*)(swk + co0 + 2);
            const ulonglong2 wb01 = *(const ulonglong2*)(swk + 32 + co0);
            const ulonglong2 wb23 = *(const ulonglong2*)(swk + 32 + co0 + 2);
#pragma unroll
            for (int i = 0; i < 4; i++) {
                const int ix = (ox0 + i) * 2 + kx;
                if (ix < 84) {
                    const ulonglong2 xv = *(const ulonglong2*)(inr + (size_t)ix * 4);
                    fma2(acc[i][0], xv.x, wa01.x);
                    fma2(acc[i][1], xv.x, wa01.y);
                    fma2(acc[i][2], xv.x, wa23.x);
                    fma2(acc[i][3], xv.x, wa23.y);
                    fma2(acc[i][0], xv.y, wb01.x);
                    fma2(acc[i][1], xv.y, wb01.y);
                    fma2(acc[i][2], xv.y, wb23.x);
                    fma2(acc[i][3], xv.y, wb23.y);
                }
            }
        }
    }
    const float4 bv = *(const float4*)(bias + co0);
    float* outr = out + ((size_t)(n * 42 + oy) * 42) * 32 + co0;
#pragma unroll
    for (int i = 0; i < 4; i++) {
        const int ox = ox0 + i;
        if (ox < 42) {
            float4 v;
            v.x = elu_(sum2(acc[i][0]) + bv.x);
            v.y = elu_(sum2(acc[i][1]) + bv.y);
            v.z = elu_(sum2(acc[i][2]) + bv.z);
            v.w = elu_(sum2(acc[i][3]) + bv.w);
            *(float4*)(outr + (size_t)ox * 32) = v;
        }
    }
}

// ---------------------------------------------------------------------------
// convN v5b: Cin=32 -> Cout=32, ci-pair f32x2, BLK=2 (128-reg budget, NO
// spill — R10's BLK=3/96-reg cap spilled: L2 28%, 1.8x slower) and large TOX
// (weight-LDS amortization). Per (kpos, quad-ci): 4 LDS.128 weights reused
// over TOX pixels; per pixel 1 LDG.128 + 8 fma2, zero broadcast movs.
// ---------------------------------------------------------------------------
template <int IH, int IW, int OH, int OW, int PAD, int TOX, int OXT, int ROWS,
          int IPB>
__global__ void __launch_bounds__(8 * OXT * ROWS * IPB, 2)
conv32_v5(const float* __restrict__ in, const float* __restrict__ w,
          const float* __restrict__ bias, float* __restrict__ out)
{
    __shared__ __align__(16) u64 sw2[9 * 16 * 32];    // 36 KB
    const int tid = threadIdx.x;
    const int NTH = 8 * OXT * ROWS * IPB;
    for (int i = tid; i < 9 * 16 * 32; i += NTH) {
        const int kpos = i >> 9, p = (i >> 5) & 15, co = i & 31;
        sw2[i] = pack2(w[(kpos * 32 + 2 * p) * 32 + co],
                       w[(kpos * 32 + 2 * p + 1) * 32 + co]);
    }
    __syncthreads();

    const int cg  = tid & 7;
    int rest      = tid >> 3;
    const int oxg = rest % OXT;  rest /= OXT;
    const int ry  = rest % ROWS;
    const int img = rest / ROWS;
    const int co0 = cg * 4;
    const int ox0 = oxg * TOX;
    const int oy  = blockIdx.x * ROWS + ry;
    const int n   = blockIdx.y * IPB + img;
    if (oy >= OH) return;

    u64 acc[TOX][4];
#pragma unroll
    for (int i = 0; i < TOX; i++)
#pragma unroll
        for (int c = 0; c < 4; c++) acc[i][c] = 0ull;

#pragma unroll 1
    for (int ky = 0; ky < 3; ky++) {
        const int iy = oy * 2 + ky - PAD;
        if (iy < 0 || iy >= IH) continue;
        const float* inr = in + ((size_t)(n * IH + iy) * IW) * 32;
#pragma unroll
        for (int kx = 0; kx < 3; kx++) {
            const u64* swk = sw2 + (ky * 3 + kx) * 16 * 32;
#pragma unroll
            for (int c4 = 0; c4 < 32; c4 += 4) {
                const int p0 = c4 >> 1;                 // even pair index
                const ulonglong2 wa01 = *(const ulonglong2*)(swk + p0 * 32 + co0);
                const ulonglong2 wa23 = *(const ulonglong2*)(swk + p0 * 32 + co0 + 2);
                const ulonglong2 wb01 = *(const ulonglong2*)(swk + (p0 + 1) * 32 + co0);
                const ulonglong2 wb23 = *(const ulonglong2*)(swk + (p0 + 1) * 32 + co0 + 2);
#pragma unroll
                for (int i = 0; i < TOX; i++) {
                    const int ix = (ox0 + i) * 2 + kx - PAD;
                    if (ix >= 0 && ix < IW) {
                        const ulonglong2 xv =
                            *(const ulonglong2*)(inr + (size_t)ix * 32 + c4);
                        fma2(acc[i][0], xv.x, wa01.x);
                        fma2(acc[i][1], xv.x, wa01.y);
                        fma2(acc[i][2], xv.x, wa23.x);
                        fma2(acc[i][3], xv.x, wa23.y);
                        fma2(acc[i][0], xv.y, wb01.x);
                        fma2(acc[i][1], xv.y, wb01.y);
                        fma2(acc[i][2], xv.y, wb23.x);
                        fma2(acc[i][3], xv.y, wb23.y);
                    }
                }
            }
        }
    }
    const float4 bv = *(const float4*)(bias + co0);
    float* outr = out + ((size_t)(n * OH + oy) * OW) * 32 + co0;
#pragma unroll
    for (int i = 0; i < TOX; i++) {
        if (ox0 + i < OW) {
            float4 v;
            v.x = elu_(sum2(acc[i][0]) + bv.x);
            v.y = elu_(sum2(acc[i][1]) + bv.y);
            v.z = elu_(sum2(acc[i][2]) + bv.z);
            v.w = elu_(sum2(acc[i][3]) + bv.w);
            *(float4*)(outr + (size_t)(ox0 + i) * 32) = v;
        }
    }
}

// ---------------------------------------------------------------------------
// SGEMM: xg[2048,1024] = c4[2048,1152] @ lstm_w[0:1152, 0:1024] + lstm_b
// 128x128x8 tiling, 256 threads, 8x8 micro-tile as f32x2 pairs over columns.
// ---------------------------------------------------------------------------
__global__ void __launch_bounds__(256, 2)
sgemm_xg_v2(const float* __restrict__ A, const float* __restrict__ B,
            const float* __restrict__ bias, float* __restrict__ C)
{
    __shared__ __align__(16) float As[8][128];
    __shared__ __align__(16) float Bs[8][128];
    const int bx  = blockIdx.x;   // 0..7   (N tiles)
    const int by  = blockIdx.y;   // 0..15  (M tiles)
    const int tid = threadIdx.x;
    const int tr  = (tid / 16) * 8;
    const int tc  = (tid % 16) * 8;

    u64 acc[8][4];
#pragma unroll
    for (int i = 0; i < 8; i++)
#pragma unroll
        for (int j = 0; j < 4; j++) acc[i][j] = 0ull;

    const int ar = tid >> 1,  ac = (tid & 1) * 4;
    const int br = tid >> 5,  bc = (tid & 31) * 4;
    const float* Aptr = A + (size_t)(by * 128 + ar) * FEAT + ac;
    const float* Bptr = B + (size_t)br * 1024 + bx * 128 + bc;

    for (int k0 = 0; k0 < FEAT; k0 += 8) {
        const float4 av = *(const float4*)(Aptr + k0);
        As[ac + 0][ar] = av.x; As[ac + 1][ar] = av.y;
        As[ac + 2][ar] = av.z; As[ac + 3][ar] = av.w;
        *(float4*)&Bs[br][bc] = *(const float4*)(Bptr + (size_t)k0 * 1024);
        __syncthreads();
#pragma unroll
        for (int kk = 0; kk < 8; kk++) {
            const float4 a0 = *(const float4*)&As[kk][tr];
            const float4 a1 = *(const float4*)&As[kk][tr + 4];
            const ulonglong2 b0 = *(const ulonglong2*)&Bs[kk][tc];
            const ulonglong2 b1 = *(const ulonglong2*)&Bs[kk][tc + 4];
            const float a[8] = {a0.x, a0.y, a0.z, a0.w, a1.x, a1.y, a1.z, a1.w};
#pragma unroll
            for (int i = 0; i < 8; i++) {
                const u64 ab = bcast2(a[i]);
                fma2(acc[i][0], ab, b0.x);
                fma2(acc[i][1], ab, b0.y);
                fma2(acc[i][2], ab, b1.x);
                fma2(acc[i][3], ab, b1.y);
            }
        }
        __syncthreads();
    }

#pragma unroll
    for (int i = 0; i < 8; i++) {
        const int row = by * 128 + tr + i;
        float* crow = C + (size_t)row * 1024 + bx * 128 + tc;
#pragma unroll
        for (int j = 0; j < 2; j++) {
            const float2 p0 = unpack2(acc[i][j * 2 + 0]);
            const float2 p1 = unpack2(acc[i][j * 2 + 1]);
            float4 v;
            v.x = p0.x + bias[bx * 128 + tc + j * 4 + 0];
            v.y = p0.y + bias[bx * 128 + tc + j * 4 + 1];
            v.z = p1.x + bias[bx * 128 + tc + j * 4 + 2];
            v.w = p1.y + bias[bx * 128 + tc + j * 4 + 3];
            *(float4*)(crow + j * 4) = v;
        }
    }
}

// ---------------------------------------------------------------------------
// Fused LSTM recurrence + FC, k-paired f32x2 (R10 form; rel_err 9e-7).
// Per k-pair: 1 LDS.64 (h pair) + 2 LDG.128 (4 gate weight pairs) + 4 fma2.
// ---------------------------------------------------------------------------
__device__ __forceinline__ float sigmoidf_(float x) { return 1.f / (1.f + expf(-x)); }

__global__ void __launch_bounds__(256)
lstm_fused_v3(const float* __restrict__ xg, const u64* __restrict__ whr2,
              const float* __restrict__ fcw, const float* __restrict__ fcb,
              const float* __restrict__ c0, const float* __restrict__ h0,
              float* __restrict__ out)
{
    const int n   = blockIdx.x;    // trajectory
    const int tid = threadIdx.x;   // hidden index
    __shared__ __align__(16) float sh[HID];

    float c = c0[(size_t)n * HID + tid];
    sh[tid] = h0[(size_t)n * HID + tid];
    __syncthreads();

    const int wrp = tid >> 5, lane = tid & 31;

    for (int t = 0; t < TL; t++) {
        const float* xrow = xg + (size_t)(n * TL + t) * 1024;
        u64 ai = pack2(xrow[tid],       0.f);
        u64 aj = pack2(xrow[256 + tid], 0.f);
        u64 af = pack2(xrow[512 + tid], 0.f);
        u64 ao = pack2(xrow[768 + tid], 0.f);

#pragma unroll 4
        for (int k2 = 0; k2 < 128; k2++) {
            const u64 h2 = *(const u64*)(sh + 2 * k2);
            const ulonglong2* wp =
                (const ulonglong2*)(whr2 + ((size_t)k2 * 256 + tid) * 4);
            const ulonglong2 w01 = wp[0];   // (i, j) pairs
            const ulonglong2 w23 = wp[1];   // (f, o) pairs
            fma2(ai, h2, w01.x);
            fma2(aj, h2, w01.y);
            fma2(af, h2, w23.x);
            fma2(ao, h2, w23.y);
        }
        const float gi = sum2(ai), gj = sum2(aj);
        const float gf = sum2(af), go = sum2(ao);

        const float nc = c * sigmoidf_(gf + 1.f) + sigmoidf_(gi) * tanhf(gj);
        const float nh = tanhf(nc) * sigmoidf_(go);
        c = nc;

        __syncthreads();
        sh[tid] = nh;
        __syncthreads();

        // FC head: 18 columns, warps 0..5 take 3 columns each
        if (wrp < 6) {
#pragma unroll
            for (int cc = 0; cc < 3; cc++) {
                const int col = wrp * 3 + cc;
                float s = 0.f;
#pragma unroll
                for (int k = lane; k < HID; k += 32) s += sh[k] * fcw[(size_t)k * NOUT + col];
#pragma unroll
                for (int off = 16; off; off >>= 1) s += __shfl_down_sync(0xffffffffu, s, off);
                if (lane == 0)
                    out[(size_t)(n * TL + t) * NOUT + col] = s + fcb[col];
            }
        }
    }
}

// ---------------------------------------------------------------------------
// Launch
// ---------------------------------------------------------------------------
extern "C" void kernel_launch(void* const* d_in, const int* in_sizes, int n_in,
                              void* d_out, int out_size)
{
    (void)in_sizes; (void)n_in; (void)out_size;
    const float* inp = (const float*)d_in[0];
    const float* w1  = (const float*)d_in[1];
    const float* b1  = (const float*)d_in[2];
    const float* w2  = (const float*)d_in[3];
    const float* b2  = (const float*)d_in[4];
    const float* w3  = (const float*)d_in[5];
    const float* b3  = (const float*)d_in[6];
    const float* w4  = (const float*)d_in[7];
    const float* b4  = (const float*)d_in[8];
    const float* lw  = (const float*)d_in[9];
    const float* lb  = (const float*)d_in[10];
    const float* fw  = (const float*)d_in[11];
    const float* fb  = (const float*)d_in[12];
    const float* c0  = (const float*)d_in[13];
    const float* h0  = (const float*)d_in[14];
    float* out = (float*)d_out;

    float *c1, *c2, *c3, *c4, *xg;
    u64* whr2;
    cudaGetSymbolAddress((void**)&c1,   g_c1);
    cudaGetSymbolAddress((void**)&c2,   g_c2);
    cudaGetSymbolAddress((void**)&c3,   g_c3);
    cudaGetSymbolAddress((void**)&c4,   g_c4);
    cudaGetSymbolAddress((void**)&xg,   g_xg);
    cudaGetSymbolAddress((void**)&whr2, g_whr2);

    // Wh reorder (independent of conv chain)
    reorder_wh2_k<<<128, 256>>>(lw, whr2);

    // conv stack — ci-pair f32x2, BLK=2 (no spill) + large TOX tiles.
    // conv1: 84->42, TOX=4, 352 thr (8cg x 11oxt x 4rows), grid (11, 2048)
    conv1_v5<<<dim3(11, NIMG), 352>>>(inp, w1, b1, c1);
    // conv2: 42->21, TOX=7 OXT=3 ROWS=8 IPB=1 -> 192 thr, grid (3, 2048)
    conv32_v5<42, 42, 21, 21, 0, 7, 3, 8, 1><<<dim3(3, NIMG), 192>>>(c1, w2, b2, c2);
    // conv3: 21->11, TOX=6 OXT=2 ROWS=12 IPB=1 -> 192 thr, grid (1, 2048)
    conv32_v5<21, 21, 11, 11, 1, 6, 2, 12, 1><<<dim3(1, NIMG), 192>>>(c2, w3, b3, c3);
    // conv4: 11->6,  TOX=6 OXT=1 ROWS=6 IPB=4 -> 192 thr, grid (1, 512)
    conv32_v5<11, 11,  6,  6, 1, 6, 1, 6, 4><<<dim3(1, NIMG / 4), 192>>>(c3, w4, b4, c4);

    // time-parallel part of the LSTM input GEMM (+ bias), f32x2 micro-kernel
    sgemm_xg_v2<<<dim3(8, 16), 256>>>(c4, lw, lb, xg);

    // recurrence + FC head fused, one persistent block per trajectory
    lstm_fused_v3<<<NT, HID>>>(xg, whr2, fw, fb, c0, h0, out);
}

// round 12
// speedup vs baseline: 1.1900x; 1.1623x over previous
#include <cuda_runtime.h>
#include <math.h>
#include <stdint.h>
#include <string.h>

// ---------------------------------------------------------------------------
// Problem constants
//   inputs [2048, 84, 84, 4] NHWC fp32
//   conv 3x3 s2 SAME x4 (ELU), channels 4->32->32->32->32
//   84 -> 42 -> 21 -> 11 -> 6   (FEAT = 6*6*32 = 1152)
//   LSTM size 256 over TL=64 steps, NT=32 trajectories, forget_bias=1
//   FC 256 -> 18
// ---------------------------------------------------------------------------

#define NIMG   2048
#define NT     32
#define TL     64
#define FEAT   1152
#define HID    256
#define NOUT   18

typedef unsigned long long u64;

// ---------------- packed f32x2 helpers (FFMA2: PTX-only pattern) -----------
__device__ __forceinline__ u64 bcast2(float x) {
    u64 d; asm("mov.b64 %0, {%1, %1};" : "=l"(d) : "f"(x)); return d;
}
__device__ __forceinline__ u64 pack2(float a, float b) {
    u64 d; asm("mov.b64 %0, {%1, %2};" : "=l"(d) : "f"(a), "f"(b)); return d;
}
__device__ __forceinline__ float2 unpack2(u64 v) {
    float2 r; asm("mov.b64 {%0, %1}, %2;" : "=f"(r.x), "=f"(r.y) : "l"(v)); return r;
}
__device__ __forceinline__ void fma2(u64& d, u64 a, u64 b) {
    asm("fma.rn.f32x2 %0, %1, %2, %0;" : "+l"(d) : "l"(a), "l"(b));
}
__device__ __forceinline__ float sum2(u64 v) {
    float2 r = unpack2(v); return r.x + r.y;
}

__device__ __forceinline__ float elu_(float v) { return v > 0.f ? v : (__expf(v) - 1.f); }

// ------------------------- device scratch (no cudaMalloc allowed) ----------
__device__ float g_c1[(size_t)NIMG * 42 * 42 * 32];   // 462 MB
__device__ float g_c2[(size_t)NIMG * 21 * 21 * 32];   // 116 MB
__device__ float g_c3[(size_t)NIMG * 11 * 11 * 32];   //  32 MB
__device__ float g_c4[(size_t)NIMG * 6 * 6 * 32];     //   9 MB
__device__ float g_xg[(size_t)NIMG * 1024];           //   8 MB  x@Wx + b
__device__ u64   g_whr2[128 * HID * 4];               //   1 MB  Wh k-paired

// ---------------------------------------------------------------------------
// Wh reorder (k-paired): whr2[(k2*256 + t)*4 + g] =
//   ( lstm_w[(1152+2*k2)*1024 + g*256 + t], lstm_w[(1152+2*k2+1)*1024 + g*256 + t] )
// ---------------------------------------------------------------------------
__global__ void reorder_wh2_k(const float* __restrict__ lw, u64* __restrict__ whr2)
{
    const int k2 = blockIdx.x;    // 0..127 (h input dim pair)
    const int t  = threadIdx.x;   // 0..255 (hidden index)
    const float* r0 = lw + (size_t)(FEAT + 2 * k2) * 1024;
    const float* r1 = lw + (size_t)(FEAT + 2 * k2 + 1) * 1024;
    u64* dst = whr2 + ((size_t)k2 * 256 + t) * 4;
    dst[0] = pack2(r0[t],       r1[t]);         // i
    dst[1] = pack2(r0[256 + t], r1[256 + t]);   // j
    dst[2] = pack2(r0[512 + t], r1[512 + t]);   // f
    dst[3] = pack2(r0[768 + t], r1[768 + t]);   // o
}

// ---------------------------------------------------------------------------
// conv1 (R8 config): Cin=4 -> Cout=32, 84x84 -> 42x42, pad_begin=0.
// One image per block, 288 threads = 8 co-groups x 6 ox-tiles(TOX=7) x 6 rows.
// f32x2 accumulators over co pairs, bcast inputs, float4-aligned weight LDS.
// ---------------------------------------------------------------------------
__global__ void __launch_bounds__(288, 2)
conv1_v3(const float* __restrict__ in, const float* __restrict__ w,
         const float* __restrict__ bias, float* __restrict__ out)
{
    __shared__ __align__(16) float sw[9 * 4 * 32];    // [kpos][ci][co]
    const int tid = threadIdx.x;
    if (tid < 288) *(float4*)(sw + tid * 4) = *(const float4*)(w + tid * 4);
    __syncthreads();

    const int cg   = tid & 7;
    const int rest = tid >> 3;
    const int oxg  = rest % 6;
    const int ry   = rest / 6;
    const int oy   = blockIdx.x * 6 + ry;             // 0..41 (7*6 exact)
    const int n    = blockIdx.y;
    const int co0  = cg * 4;
    const int ox0  = oxg * 7;                          // 6*7 = 42 exact

    u64 aL[7], aH[7];
    const u64 bL = pack2(bias[co0],     bias[co0 + 1]);
    const u64 bH = pack2(bias[co0 + 2], bias[co0 + 3]);
#pragma unroll
    for (int i = 0; i < 7; i++) { aL[i] = bL; aH[i] = bH; }

#pragma unroll 1
    for (int ky = 0; ky < 3; ky++) {
        const int iy = oy * 2 + ky;
        if (iy >= 84) continue;
        const float* inr = in + ((size_t)(n * 84 + iy) * 84) * 4;
#pragma unroll
        for (int kx = 0; kx < 3; kx++) {
            const float* swk = sw + ((ky * 3 + kx) * 4) * 32 + co0;
            const ulonglong2 w0 = *(const ulonglong2*)(swk);
            const ulonglong2 w1 = *(const ulonglong2*)(swk + 32);
            const ulonglong2 w2 = *(const ulonglong2*)(swk + 64);
            const ulonglong2 w3 = *(const ulonglong2*)(swk + 96);
#pragma unroll
            for (int i = 0; i < 7; i++) {
                const int ix = (ox0 + i) * 2 + kx;
                if (ix < 84) {
                    const float4 x = *(const float4*)(inr + (size_t)ix * 4);
                    u64 xb;
                    xb = bcast2(x.x); fma2(aL[i], xb, w0.x); fma2(aH[i], xb, w0.y);
                    xb = bcast2(x.y); fma2(aL[i], xb, w1.x); fma2(aH[i], xb, w1.y);
                    xb = bcast2(x.z); fma2(aL[i], xb, w2.x); fma2(aH[i], xb, w2.y);
                    xb = bcast2(x.w); fma2(aL[i], xb, w3.x); fma2(aH[i], xb, w3.y);
                }
            }
        }
    }
    float* outr = out + ((size_t)(n * 42 + oy) * 42) * 32 + co0;
#pragma unroll
    for (int i = 0; i < 7; i++) {
        const float2 lo = unpack2(aL[i]), hi = unpack2(aH[i]);
        float4 v;
        v.x = elu_(lo.x); v.y = elu_(lo.y); v.z = elu_(hi.x); v.w = elu_(hi.y);
        *(float4*)(outr + (size_t)(ox0 + i) * 32) = v;
    }
}

// ---------------------------------------------------------------------------
// convN (R8 code, BLK templated): Cin=32 -> Cout=32, f32x2 over co pairs,
// bcast inputs, 16B-strided float4 weight LDS (conflict-free across cg).
// Per-layer (TOX, BLK) chosen from measured profiles:
//   big tile + BLK=2 (no spill, R8) or small tile + BLK=3 (96 regs, R9).
// ---------------------------------------------------------------------------
template <int IH, int IW, int OH, int OW, int PAD, int TOX, int OXT, int ROWS,
          int IPB, int BLK>
__global__ void __launch_bounds__(8 * OXT * ROWS * IPB, BLK)
conv32_v3(const float* __restrict__ in, const float* __restrict__ w,
          const float* __restrict__ bias, float* __restrict__ out)
{
    __shared__ __align__(16) float sw[9 * 32 * 32];   // [kpos][ci][co] = 36 KB
    const int tid = threadIdx.x;
    const int NTH = 8 * OXT * ROWS * IPB;
    for (int i = tid * 4; i < 9 * 32 * 32; i += NTH * 4)
        *(float4*)(sw + i) = *(const float4*)(w + i);
    __syncthreads();

    const int cg  = tid & 7;
    int rest      = tid >> 3;
    const int oxg = rest % OXT;  rest /= OXT;
    const int ry  = rest % ROWS;
    const int img = rest / ROWS;
    const int co0 = cg * 4;
    const int ox0 = oxg * TOX;
    const int oy  = blockIdx.x * ROWS + ry;
    const int n   = blockIdx.y * IPB + img;
    if (oy >= OH) return;

    u64 aL[TOX], aH[TOX];
    const u64 bL = pack2(bias[co0],     bias[co0 + 1]);
    const u64 bH = pack2(bias[co0 + 2], bias[co0 + 3]);
#pragma unroll
    for (int i = 0; i < TOX; i++) { aL[i] = bL; aH[i] = bH; }

#pragma unroll 1
    for (int ky = 0; ky < 3; ky++) {
        const int iy = oy * 2 + ky - PAD;
        if (iy < 0 || iy >= IH) continue;
        const float* inr = in + ((size_t)(n * IH + iy) * IW) * 32;
#pragma unroll
        for (int kx = 0; kx < 3; kx++) {
            const float* swk = sw + ((ky * 3 + kx) * 32) * 32 + co0;
#pragma unroll
            for (int c4 = 0; c4 < 32; c4 += 4) {
                const ulonglong2 w0 = *(const ulonglong2*)(swk + (c4 + 0) * 32);
                const ulonglong2 w1 = *(const ulonglong2*)(swk + (c4 + 1) * 32);
                const ulonglong2 w2 = *(const ulonglong2*)(swk + (c4 + 2) * 32);
                const ulonglong2 w3 = *(const ulonglong2*)(swk + (c4 + 3) * 32);
#pragma unroll
                for (int i = 0; i < TOX; i++) {
                    const int ix = (ox0 + i) * 2 + kx - PAD;
                    if (ix >= 0 && ix < IW) {
                        const float4 x = *(const float4*)(inr + (size_t)ix * 32 + c4);
                        u64 xb;
                        xb = bcast2(x.x); fma2(aL[i], xb, w0.x); fma2(aH[i], xb, w0.y);
                        xb = bcast2(x.y); fma2(aL[i], xb, w1.x); fma2(aH[i], xb, w1.y);
                        xb = bcast2(x.z); fma2(aL[i], xb, w2.x); fma2(aH[i], xb, w2.y);
                        xb = bcast2(x.w); fma2(aL[i], xb, w3.x); fma2(aH[i], xb, w3.y);
                    }
                }
            }
        }
    }
    float* outr = out + ((size_t)(n * OH + oy) * OW) * 32 + co0;
#pragma unroll
    for (int i = 0; i < TOX; i++) {
        if (ox0 + i < OW) {
            const float2 lo = unpack2(aL[i]), hi = unpack2(aH[i]);
            float4 v;
            v.x = elu_(lo.x); v.y = elu_(lo.y); v.z = elu_(hi.x); v.w = elu_(hi.y);
            *(float4*)(outr + (size_t)(ox0 + i) * 32) = v;
        }
    }
}

// ---------------------------------------------------------------------------
// SGEMM: xg[2048,1024] = c4[2048,1152] @ lstm_w[0:1152, 0:1024] + lstm_b
// 128x128x8 tiling, 256 threads, 8x8 micro-tile as f32x2 pairs over columns.
// ---------------------------------------------------------------------------
__global__ void __launch_bounds__(256, 2)
sgemm_xg_v2(const float* __restrict__ A, const float* __restrict__ B,
            const float* __restrict__ bias, float* __restrict__ C)
{
    __shared__ __align__(16) float As[8][128];
    __shared__ __align__(16) float Bs[8][128];
    const int bx  = blockIdx.x;   // 0..7   (N tiles)
    const int by  = blockIdx.y;   // 0..15  (M tiles)
    const int tid = threadIdx.x;
    const int tr  = (tid / 16) * 8;
    const int tc  = (tid % 16) * 8;

    u64 acc[8][4];
#pragma unroll
    for (int i = 0; i < 8; i++)
#pragma unroll
        for (int j = 0; j < 4; j++) acc[i][j] = 0ull;

    const int ar = tid >> 1,  ac = (tid & 1) * 4;
    const int br = tid >> 5,  bc = (tid & 31) * 4;
    const float* Aptr = A + (size_t)(by * 128 + ar) * FEAT + ac;
    const float* Bptr = B + (size_t)br * 1024 + bx * 128 + bc;

    for (int k0 = 0; k0 < FEAT; k0 += 8) {
        const float4 av = *(const float4*)(Aptr + k0);
        As[ac + 0][ar] = av.x; As[ac + 1][ar] = av.y;
        As[ac + 2][ar] = av.z; As[ac + 3][ar] = av.w;
        *(float4*)&Bs[br][bc] = *(const float4*)(Bptr + (size_t)k0 * 1024);
        __syncthreads();
#pragma unroll
        for (int kk = 0; kk < 8; kk++) {
            const float4 a0 = *(const float4*)&As[kk][tr];
            const float4 a1 = *(const float4*)&As[kk][tr + 4];
            const ulonglong2 b0 = *(const ulonglong2*)&Bs[kk][tc];
            const ulonglong2 b1 = *(const ulonglong2*)&Bs[kk][tc + 4];
            const float a[8] = {a0.x, a0.y, a0.z, a0.w, a1.x, a1.y, a1.z, a1.w};
#pragma unroll
            for (int i = 0; i < 8; i++) {
                const u64 ab = bcast2(a[i]);
                fma2(acc[i][0], ab, b0.x);
                fma2(acc[i][1], ab, b0.y);
                fma2(acc[i][2], ab, b1.x);
                fma2(acc[i][3], ab, b1.y);
            }
        }
        __syncthreads();
    }

#pragma unroll
    for (int i = 0; i < 8; i++) {
        const int row = by * 128 + tr + i;
        float* crow = C + (size_t)row * 1024 + bx * 128 + tc;
#pragma unroll
        for (int j = 0; j < 2; j++) {
            const float2 p0 = unpack2(acc[i][j * 2 + 0]);
            const float2 p1 = unpack2(acc[i][j * 2 + 1]);
            float4 v;
            v.x = p0.x + bias[bx * 128 + tc + j * 4 + 0];
            v.y = p0.y + bias[bx * 128 + tc + j * 4 + 1];
            v.z = p1.x + bias[bx * 128 + tc + j * 4 + 2];
            v.w = p1.y + bias[bx * 128 + tc + j * 4 + 3];
            *(float4*)(crow + j * 4) = v;
        }
    }
}

// ---------------------------------------------------------------------------
// Fused LSTM recurrence + FC, k-paired f32x2 (rel_err 9e-7).
// Per k-pair: 1 LDS.64 (h pair) + 2 LDG.128 (4 gate weight pairs) + 4 fma2.
// ---------------------------------------------------------------------------
__device__ __forceinline__ float sigmoidf_(float x) { return 1.f / (1.f + expf(-x)); }

__global__ void __launch_bounds__(256)
lstm_fused_v3(const float* __restrict__ xg, const u64* __restrict__ whr2,
              const float* __restrict__ fcw, const float* __restrict__ fcb,
              const float* __restrict__ c0, const float* __restrict__ h0,
              float* __restrict__ out)
{
    const int n   = blockIdx.x;    // trajectory
    const int tid = threadIdx.x;   // hidden index
    __shared__ __align__(16) float sh[HID];

    float c = c0[(size_t)n * HID + tid];
    sh[tid] = h0[(size_t)n * HID + tid];
    __syncthreads();

    const int wrp = tid >> 5, lane = tid & 31;

    for (int t = 0; t < TL; t++) {
        const float* xrow = xg + (size_t)(n * TL + t) * 1024;
        u64 ai = pack2(xrow[tid],       0.f);
        u64 aj = pack2(xrow[256 + tid], 0.f);
        u64 af = pack2(xrow[512 + tid], 0.f);
        u64 ao = pack2(xrow[768 + tid], 0.f);

#pragma unroll 4
        for (int k2 = 0; k2 < 128; k2++) {
            const u64 h2 = *(const u64*)(sh + 2 * k2);
            const ulonglong2* wp =
                (const ulonglong2*)(whr2 + ((size_t)k2 * 256 + tid) * 4);
            const ulonglong2 w01 = wp[0];   // (i, j) pairs
            const ulonglong2 w23 = wp[1];   // (f, o) pairs
            fma2(ai, h2, w01.x);
            fma2(aj, h2, w01.y);
            fma2(af, h2, w23.x);
            fma2(ao, h2, w23.y);
        }
        const float gi = sum2(ai), gj = sum2(aj);
        const float gf = sum2(af), go = sum2(ao);

        const float nc = c * sigmoidf_(gf + 1.f) + sigmoidf_(gi) * tanhf(gj);
        const float nh = tanhf(nc) * sigmoidf_(go);
        c = nc;

        __syncthreads();
        sh[tid] = nh;
        __syncthreads();

        // FC head: 18 columns, warps 0..5 take 3 columns each
        if (wrp < 6) {
#pragma unroll
            for (int cc = 0; cc < 3; cc++) {
                const int col = wrp * 3 + cc;
                float s = 0.f;
#pragma unroll
                for (int k = lane; k < HID; k += 32) s += sh[k] * fcw[(size_t)k * NOUT + col];
#pragma unroll
                for (int off = 16; off; off >>= 1) s += __shfl_down_sync(0xffffffffu, s, off);
                if (lane == 0)
                    out[(size_t)(n * TL + t) * NOUT + col] = s + fcb[col];
            }
        }
    }
}

// ---------------------------------------------------------------------------
// Launch
// ---------------------------------------------------------------------------
extern "C" void kernel_launch(void* const* d_in, const int* in_sizes, int n_in,
                              void* d_out, int out_size)
{
    (void)in_sizes; (void)n_in; (void)out_size;
    const float* inp = (const float*)d_in[0];
    const float* w1  = (const float*)d_in[1];
    const float* b1  = (const float*)d_in[2];
    const float* w2  = (const float*)d_in[3];
    const float* b2  = (const float*)d_in[4];
    const float* w3  = (const float*)d_in[5];
    const float* b3  = (const float*)d_in[6];
    const float* w4  = (const float*)d_in[7];
    const float* b4  = (const float*)d_in[8];
    const float* lw  = (const float*)d_in[9];
    const float* lb  = (const float*)d_in[10];
    const float* fw  = (const float*)d_in[11];
    const float* fb  = (const float*)d_in[12];
    const float* c0  = (const float*)d_in[13];
    const float* h0  = (const float*)d_in[14];
    float* out = (float*)d_out;

    float *c1, *c2, *c3, *c4, *xg;
    u64* whr2;
    cudaGetSymbolAddress((void**)&c1,   g_c1);
    cudaGetSymbolAddress((void**)&c2,   g_c2);
    cudaGetSymbolAddress((void**)&c3,   g_c3);
    cudaGetSymbolAddress((void**)&c4,   g_c4);
    cudaGetSymbolAddress((void**)&xg,   g_xg);
    cudaGetSymbolAddress((void**)&whr2, g_whr2);

    // Wh reorder (independent of conv chain)
    reorder_wh2_k<<<128, 256>>>(lw, whr2);

    // conv stack — measured-best per-layer configs:
    // conv1 (R8): 84->42, TOX=7, 288 thr, grid (7, 2048)
    conv1_v3<<<dim3(7, NIMG), 288>>>(inp, w1, b1, c1);
    // conv2 (R8): 42->21, TOX=7 OXT=3 ROWS=8 IPB=1 BLK=2 -> 192 thr, grid (3, 2048)
    conv32_v3<42, 42, 21, 21, 0, 7, 3, 8, 1, 2><<<dim3(3, NIMG), 192>>>(c1, w2, b2, c2);
    // conv3 (R9, measured 180us/96regs/no-spill): TOX=3 OXT=4 ROWS=6 IPB=1 BLK=3
    conv32_v3<21, 21, 11, 11, 1, 3, 4, 6, 1, 3><<<dim3(2, NIMG), 192>>>(c2, w3, b3, c3);
    // conv4 (R8): 11->6, TOX=6 OXT=1 ROWS=6 IPB=4 BLK=2 -> 192 thr, grid (1, 512)
    conv32_v3<11, 11,  6,  6, 1, 6, 1, 6, 4, 2><<<dim3(1, NIMG / 4), 192>>>(c3, w4, b4, c4);

    // time-parallel part of the LSTM input GEMM (+ bias), f32x2 micro-kernel
    sgemm_xg_v2<<<dim3(8, 16), 256>>>(c4, lw, lb, xg);

    // recurrence + FC head fused, one persistent block per trajectory
    lstm_fused_v3<<<NT, HID>>>(xg, whr2, fw, fb, c0, h0, out);
}

// round 13
// speedup vs baseline: 1.2208x; 1.0259x over previous
#include <cuda_runtime.h>
#include <math.h>
#include <stdint.h>
#include <string.h>

// ---------------------------------------------------------------------------
// Problem constants
// ---------------------------------------------------------------------------
#define NIMG   2048
#define NT     32
#define TL     64
#define FEAT   1152
#define HID    256
#define NOUT   18

typedef unsigned long long u64;

// ---------------- packed f32x2 helpers (FFMA2: PTX-only pattern) -----------
__device__ __forceinline__ u64 bcast2(float x) {
    u64 d; asm("mov.b64 %0, {%1, %1};" : "=l"(d) : "f"(x)); return d;
}
__device__ __forceinline__ u64 pack2(float a, float b) {
    u64 d; asm("mov.b64 %0, {%1, %2};" : "=l"(d) : "f"(a), "f"(b)); return d;
}
__device__ __forceinline__ float2 unpack2(u64 v) {
    float2 r; asm("mov.b64 {%0, %1}, %2;" : "=f"(r.x), "=f"(r.y) : "l"(v)); return r;
}
__device__ __forceinline__ void fma2(u64& d, u64 a, u64 b) {
    asm("fma.rn.f32x2 %0, %1, %2, %0;" : "+l"(d) : "l"(a), "l"(b));
}
__device__ __forceinline__ float sum2(u64 v) {
    float2 r = unpack2(v); return r.x + r.y;
}

__device__ __forceinline__ float elu_(float v) { return v > 0.f ? v : (__expf(v) - 1.f); }

// ------------------------- device scratch (no cudaMalloc allowed) ----------
__device__ float g_c1[(size_t)NIMG * 42 * 42 * 32];   // 462 MB
__device__ float g_c2[(size_t)NIMG * 21 * 21 * 32];   // 116 MB
__device__ float g_c3[(size_t)NIMG * 11 * 11 * 32];   //  32 MB
__device__ float g_c4[(size_t)NIMG * 6 * 6 * 32];     //   9 MB
__device__ float g_xg[(size_t)NIMG * 1024];           //   8 MB  x@Wx + b
__device__ u64   g_whr2[128 * HID * 4];               //   1 MB  Wh k-paired

// ---------------------------------------------------------------------------
// Wh reorder (k-paired)
// ---------------------------------------------------------------------------
__global__ void reorder_wh2_k(const float* __restrict__ lw, u64* __restrict__ whr2)
{
    const int k2 = blockIdx.x;    // 0..127
    const int t  = threadIdx.x;   // 0..255
    const float* r0 = lw + (size_t)(FEAT + 2 * k2) * 1024;
    const float* r1 = lw + (size_t)(FEAT + 2 * k2 + 1) * 1024;
    u64* dst = whr2 + ((size_t)k2 * 256 + t) * 4;
    dst[0] = pack2(r0[t],       r1[t]);         // i
    dst[1] = pack2(r0[256 + t], r1[256 + t]);   // j
    dst[2] = pack2(r0[512 + t], r1[512 + t]);   // f
    dst[3] = pack2(r0[768 + t], r1[768 + t]);   // o
}

// ---------------------------------------------------------------------------
// conv1 v6 (TOY=2): Cin=4 -> Cout=32, 84x84 -> 42x42, pad_begin=0.
// Each thread: 2 output rows x TOX=4 pixels x 4 co. Weight LDS reused over
// 2*TOX pixels. 352 threads = 8cg x 11oxt x 4 row-pairs; one image per block.
// ---------------------------------------------------------------------------
__global__ void __launch_bounds__(352, 2)
conv1_v6(const float* __restrict__ in, const float* __restrict__ w,
         const float* __restrict__ bias, float* __restrict__ out)
{
    __shared__ __align__(16) float sw[9 * 4 * 32];    // [kpos][ci][co]
    const int tid = threadIdx.x;
    if (tid < 288) *(float4*)(sw + tid * 4) = *(const float4*)(w + tid * 4);
    __syncthreads();

    const int cg   = tid & 7;
    const int rest = tid >> 3;
    const int oxg  = rest % 11;
    const int rp   = rest / 11;
    const int pair = blockIdx.x * 4 + rp;             // 0..23, valid 0..20
    const int oyA  = 2 * pair;
    const int n    = blockIdx.y;
    const int co0  = cg * 4;
    const int ox0  = oxg * 4;
    if (oyA >= 42) return;
    const bool hasB = (oyA + 1) < 42;

    u64 aAL[4], aAH[4], aBL[4], aBH[4];
    const u64 bL = pack2(bias[co0],     bias[co0 + 1]);
    const u64 bH = pack2(bias[co0 + 2], bias[co0 + 3]);
#pragma unroll
    for (int i = 0; i < 4; i++) { aAL[i] = bL; aAH[i] = bH; aBL[i] = bL; aBH[i] = bH; }

#pragma unroll 1
    for (int ky = 0; ky < 3; ky++) {
        const int iyA = oyA * 2 + ky;                 // pad_begin=0
        const int iyB = iyA + 2;
        const bool okA = iyA < 84;
        const bool okB = hasB && iyB < 84;
        if (!okA && !okB) continue;
        const float* inA = in + ((size_t)(n * 84 + iyA) * 84) * 4;
        const float* inB = in + ((size_t)(n * 84 + iyB) * 84) * 4;
#pragma unroll
        for (int kx = 0; kx < 3; kx++) {
            const float* swk = sw + ((ky * 3 + kx) * 4) * 32 + co0;
            const ulonglong2 w0 = *(const ulonglong2*)(swk);
            const ulonglong2 w1 = *(const ulonglong2*)(swk + 32);
            const ulonglong2 w2 = *(const ulonglong2*)(swk + 64);
            const ulonglong2 w3 = *(const ulonglong2*)(swk + 96);
#pragma unroll
            for (int i = 0; i < 4; i++) {
                const int ix = (ox0 + i) * 2 + kx;
                if (ix < 84) {
                    if (okA) {
                        const float4 x = *(const float4*)(inA + (size_t)ix * 4);
                        u64 xb;
                        xb = bcast2(x.x); fma2(aAL[i], xb, w0.x); fma2(aAH[i], xb, w0.y);
                        xb = bcast2(x.y); fma2(aAL[i], xb, w1.x); fma2(aAH[i], xb, w1.y);
                        xb = bcast2(x.z); fma2(aAL[i], xb, w2.x); fma2(aAH[i], xb, w2.y);
                        xb = bcast2(x.w); fma2(aAL[i], xb, w3.x); fma2(aAH[i], xb, w3.y);
                    }
                    if (okB) {
                        const float4 x = *(const float4*)(inB + (size_t)ix * 4);
                        u64 xb;
                        xb = bcast2(x.x); fma2(aBL[i], xb, w0.x); fma2(aBH[i], xb, w0.y);
                        xb = bcast2(x.y); fma2(aBL[i], xb, w1.x); fma2(aBH[i], xb, w1.y);
                        xb = bcast2(x.z); fma2(aBL[i], xb, w2.x); fma2(aBH[i], xb, w2.y);
                        xb = bcast2(x.w); fma2(aBL[i], xb, w3.x); fma2(aBH[i], xb, w3.y);
                    }
                }
            }
        }
    }
    float* outA = out + ((size_t)(n * 42 + oyA) * 42) * 32 + co0;
#pragma unroll
    for (int i = 0; i < 4; i++) {
        const int ox = ox0 + i;
        if (ox < 42) {
            const float2 lo = unpack2(aAL[i]), hi = unpack2(aAH[i]);
            float4 v;
            v.x = elu_(lo.x); v.y = elu_(lo.y); v.z = elu_(hi.x); v.w = elu_(hi.y);
            *(float4*)(outA + (size_t)ox * 32) = v;
        }
    }
    if (hasB) {
        float* outB = out + ((size_t)(n * 42 + oyA + 1) * 42) * 32 + co0;
#pragma unroll
        for (int i = 0; i < 4; i++) {
            const int ox = ox0 + i;
            if (ox < 42) {
                const float2 lo = unpack2(aBL[i]), hi = unpack2(aBH[i]);
                float4 v;
                v.x = elu_(lo.x); v.y = elu_(lo.y); v.z = elu_(hi.x); v.w = elu_(hi.y);
                *(float4*)(outB + (size_t)ox * 32) = v;
            }
        }
    }
}

// ---------------------------------------------------------------------------
// convN v6 (TOY=2): Cin=32 -> Cout=32. Each thread: 2 output rows x TOX x 4co.
// Per (ky,kx,c4): 4 LDS.128 weights feed 2*TOX pixels (vs TOX before):
// L1 ops per 96 MACs drop 8LDS+6LDG -> 4LDS+6LDG (-29%). BLK=2, no reg cap.
// ---------------------------------------------------------------------------
template <int IH, int IW, int OH, int OW, int PAD, int TOX, int OXT, int RP>
__global__ void __launch_bounds__(8 * OXT * RP, 2)
conv32_v6(const float* __restrict__ in, const float* __restrict__ w,
          const float* __restrict__ bias, float* __restrict__ out)
{
    __shared__ __align__(16) float sw[9 * 32 * 32];   // 36 KB
    const int tid = threadIdx.x;
    const int NTH = 8 * OXT * RP;
    for (int i = tid * 4; i < 9 * 32 * 32; i += NTH * 4)
        *(float4*)(sw + i) = *(const float4*)(w + i);
    __syncthreads();

    const int cg   = tid & 7;
    int rest       = tid >> 3;
    const int oxg  = rest % OXT;
    const int rp   = rest / OXT;
    const int pair = blockIdx.x * RP + rp;
    const int oyA  = 2 * pair;
    const int n    = blockIdx.y;
    const int co0  = cg * 4;
    const int ox0  = oxg * TOX;
    if (oyA >= OH) return;
    const bool hasB = (oyA + 1) < OH;

    u64 aAL[TOX], aAH[TOX], aBL[TOX], aBH[TOX];
    const u64 bL = pack2(bias[co0],     bias[co0 + 1]);
    const u64 bH = pack2(bias[co0 + 2], bias[co0 + 3]);
#pragma unroll
    for (int i = 0; i < TOX; i++) { aAL[i] = bL; aAH[i] = bH; aBL[i] = bL; aBH[i] = bH; }

#pragma unroll 1
    for (int ky = 0; ky < 3; ky++) {
        const int iyA = oyA * 2 + ky - PAD;
        const int iyB = iyA + 2;
        const bool okA = (iyA >= 0) && (iyA < IH);
        const bool okB = hasB && (iyB < IH);          // iyB >= 1 always
        if (!okA && !okB) continue;
        const float* inA = in + ((size_t)(n * IH + iyA) * IW) * 32;
        const float* inB = in + ((size_t)(n * IH + iyB) * IW) * 32;
#pragma unroll
        for (int kx = 0; kx < 3; kx++) {
            const float* swk = sw + ((ky * 3 + kx) * 32) * 32 + co0;
#pragma unroll
            for (int c4 = 0; c4 < 32; c4 += 4) {
                const ulonglong2 w0 = *(const ulonglong2*)(swk + (c4 + 0) * 32);
                const ulonglong2 w1 = *(const ulonglong2*)(swk + (c4 + 1) * 32);
                const ulonglong2 w2 = *(const ulonglong2*)(swk + (c4 + 2) * 32);
                const ulonglong2 w3 = *(const ulonglong2*)(swk + (c4 + 3) * 32);
#pragma unroll
                for (int i = 0; i < TOX; i++) {
                    const int ix = (ox0 + i) * 2 + kx - PAD;
                    if (ix >= 0 && ix < IW) {
                        if (okA) {
                            const float4 x = *(const float4*)(inA + (size_t)ix * 32 + c4);
                            u64 xb;
                            xb = bcast2(x.x); fma2(aAL[i], xb, w0.x); fma2(aAH[i], xb, w0.y);
                            xb = bcast2(x.y); fma2(aAL[i], xb, w1.x); fma2(aAH[i], xb, w1.y);
                            xb = bcast2(x.z); fma2(aAL[i], xb, w2.x); fma2(aAH[i], xb, w2.y);
                            xb = bcast2(x.w); fma2(aAL[i], xb, w3.x); fma2(aAH[i], xb, w3.y);
                        }
                        if (okB) {
                            const float4 x = *(const float4*)(inB + (size_t)ix * 32 + c4);
                            u64 xb;
                            xb = bcast2(x.x); fma2(aBL[i], xb, w0.x); fma2(aBH[i], xb, w0.y);
                            xb = bcast2(x.y); fma2(aBL[i], xb, w1.x); fma2(aBH[i], xb, w1.y);
                            xb = bcast2(x.z); fma2(aBL[i], xb, w2.x); fma2(aBH[i], xb, w2.y);
                            xb = bcast2(x.w); fma2(aBL[i], xb, w3.x); fma2(aBH[i], xb, w3.y);
                        }
                    }
                }
            }
        }
    }
    float* outA = out + ((size_t)(n * OH + oyA) * OW) * 32 + co0;
#pragma unroll
    for (int i = 0; i < TOX; i++) {
        if (ox0 + i < OW) {
            const float2 lo = unpack2(aAL[i]), hi = unpack2(aAH[i]);
            float4 v;
            v.x = elu_(lo.x); v.y = elu_(lo.y); v.z = elu_(hi.x); v.w = elu_(hi.y);
            *(float4*)(outA + (size_t)(ox0 + i) * 32) = v;
        }
    }
    if (hasB) {
        float* outB = out + ((size_t)(n * OH + oyA + 1) * OW) * 32 + co0;
#pragma unroll
        for (int i = 0; i < TOX; i++) {
            if (ox0 + i < OW) {
                const float2 lo = unpack2(aBL[i]), hi = unpack2(aBH[i]);
                float4 v;
                v.x = elu_(lo.x); v.y = elu_(lo.y); v.z = elu_(hi.x); v.w = elu_(hi.y);
                *(float4*)(outB + (size_t)(ox0 + i) * 32) = v;
            }
        }
    }
}

// ---------------------------------------------------------------------------
// conv4 (R8 config, unchanged): single-row, TOX=6, IPB=4, BLK=2
// ---------------------------------------------------------------------------
template <int IH, int IW, int OH, int OW, int PAD, int TOX, int OXT, int ROWS,
          int IPB, int BLK>
__global__ void __launch_bounds__(8 * OXT * ROWS * IPB, BLK)
conv32_v3(const float* __restrict__ in, const float* __restrict__ w,
          const float* __restrict__ bias, float* __restrict__ out)
{
    __shared__ __align__(16) float sw[9 * 32 * 32];
    const int tid = threadIdx.x;
    const int NTH = 8 * OXT * ROWS * IPB;
    for (int i = tid * 4; i < 9 * 32 * 32; i += NTH * 4)
        *(float4*)(sw + i) = *(const float4*)(w + i);
    __syncthreads();

    const int cg  = tid & 7;
    int rest      = tid >> 3;
    const int oxg = rest % OXT;  rest /= OXT;
    const int ry  = rest % ROWS;
    const int img = rest / ROWS;
    const int co0 = cg * 4;
    const int ox0 = oxg * TOX;
    const int oy  = blockIdx.x * ROWS + ry;
    const int n   = blockIdx.y * IPB + img;
    if (oy >= OH) return;

    u64 aL[TOX], aH[TOX];
    const u64 bL = pack2(bias[co0],     bias[co0 + 1]);
    const u64 bH = pack2(bias[co0 + 2], bias[co0 + 3]);
#pragma unroll
    for (int i = 0; i < TOX; i++) { aL[i] = bL; aH[i] = bH; }

#pragma unroll 1
    for (int ky = 0; ky < 3; ky++) {
        const int iy = oy * 2 + ky - PAD;
        if (iy < 0 || iy >= IH) continue;
        const float* inr = in + ((size_t)(n * IH + iy) * IW) * 32;
#pragma unroll
        for (int kx = 0; kx < 3; kx++) {
            const float* swk = sw + ((ky * 3 + kx) * 32) * 32 + co0;
#pragma unroll
            for (int c4 = 0; c4 < 32; c4 += 4) {
                const ulonglong2 w0 = *(const ulonglong2*)(swk + (c4 + 0) * 32);
                const ulonglong2 w1 = *(const ulonglong2*)(swk + (c4 + 1) * 32);
                const ulonglong2 w2 = *(const ulonglong2*)(swk + (c4 + 2) * 32);
                const ulonglong2 w3 = *(const ulonglong2*)(swk + (c4 + 3) * 32);
#pragma unroll
                for (int i = 0; i < TOX; i++) {
                    const int ix = (ox0 + i) * 2 + kx - PAD;
                    if (ix >= 0 && ix < IW) {
                        const float4 x = *(const float4*)(inr + (size_t)ix * 32 + c4);
                        u64 xb;
                        xb = bcast2(x.x); fma2(aL[i], xb, w0.x); fma2(aH[i], xb, w0.y);
                        xb = bcast2(x.y); fma2(aL[i], xb, w1.x); fma2(aH[i], xb, w1.y);
                        xb = bcast2(x.z); fma2(aL[i], xb, w2.x); fma2(aH[i], xb, w2.y);
                        xb = bcast2(x.w); fma2(aL[i], xb, w3.x); fma2(aH[i], xb, w3.y);
                    }
                }
            }
        }
    }
    float* outr = out + ((size_t)(n * OH + oy) * OW) * 32 + co0;
#pragma unroll
    for (int i = 0; i < TOX; i++) {
        if (ox0 + i < OW) {
            const float2 lo = unpack2(aL[i]), hi = unpack2(aH[i]);
            float4 v;
            v.x = elu_(lo.x); v.y = elu_(lo.y); v.z = elu_(hi.x); v.w = elu_(hi.y);
            *(float4*)(outr + (size_t)(ox0 + i) * 32) = v;
        }
    }
}

// ---------------------------------------------------------------------------
// SGEMM (unchanged)
// ---------------------------------------------------------------------------
__global__ void __launch_bounds__(256, 2)
sgemm_xg_v2(const float* __restrict__ A, const float* __restrict__ B,
            const float* __restrict__ bias, float* __restrict__ C)
{
    __shared__ __align__(16) float As[8][128];
    __shared__ __align__(16) float Bs[8][128];
    const int bx  = blockIdx.x;
    const int by  = blockIdx.y;
    const int tid = threadIdx.x;
    const int tr  = (tid / 16) * 8;
    const int tc  = (tid % 16) * 8;

    u64 acc[8][4];
#pragma unroll
    for (int i = 0; i < 8; i++)
#pragma unroll
        for (int j = 0; j < 4; j++) acc[i][j] = 0ull;

    const int ar = tid >> 1,  ac = (tid & 1) * 4;
    const int br = tid >> 5,  bc = (tid & 31) * 4;
    const float* Aptr = A + (size_t)(by * 128 + ar) * FEAT + ac;
    const float* Bptr = B + (size_t)br * 1024 + bx * 128 + bc;

    for (int k0 = 0; k0 < FEAT; k0 += 8) {
        const float4 av = *(const float4*)(Aptr + k0);
        As[ac + 0][ar] = av.x; As[ac + 1][ar] = av.y;
        As[ac + 2][ar] = av.z; As[ac + 3][ar] = av.w;
        *(float4*)&Bs[br][bc] = *(const float4*)(Bptr + (size_t)k0 * 1024);
        __syncthreads();
#pragma unroll
        for (int kk = 0; kk < 8; kk++) {
            const float4 a0 = *(const float4*)&As[kk][tr];
            const float4 a1 = *(const float4*)&As[kk][tr + 4];
            const ulonglong2 b0 = *(const ulonglong2*)&Bs[kk][tc];
            const ulonglong2 b1 = *(const ulonglong2*)&Bs[kk][tc + 4];
            const float a[8] = {a0.x, a0.y, a0.z, a0.w, a1.x, a1.y, a1.z, a1.w};
#pragma unroll
            for (int i = 0; i < 8; i++) {
                const u64 ab = bcast2(a[i]);
                fma2(acc[i][0], ab, b0.x);
                fma2(acc[i][1], ab, b0.y);
                fma2(acc[i][2], ab, b1.x);
                fma2(acc[i][3], ab, b1.y);
            }
        }
        __syncthreads();
    }

#pragma unroll
    for (int i = 0; i < 8; i++) {
        const int row = by * 128 + tr + i;
        float* crow = C + (size_t)row * 1024 + bx * 128 + tc;
#pragma unroll
        for (int j = 0; j < 2; j++) {
            const float2 p0 = unpack2(acc[i][j * 2 + 0]);
            const float2 p1 = unpack2(acc[i][j * 2 + 1]);
            float4 v;
            v.x = p0.x + bias[bx * 128 + tc + j * 4 + 0];
            v.y = p0.y + bias[bx * 128 + tc + j * 4 + 1];
            v.z = p1.x + bias[bx * 128 + tc + j * 4 + 2];
            v.w = p1.y + bias[bx * 128 + tc + j * 4 + 3];
            *(float4*)(crow + j * 4) = v;
        }
    }
}

// ---------------------------------------------------------------------------
// Fused LSTM recurrence + FC (unchanged)
// ---------------------------------------------------------------------------
__device__ __forceinline__ float sigmoidf_(float x) { return 1.f / (1.f + expf(-x)); }

__global__ void __launch_bounds__(256)
lstm_fused_v3(const float* __restrict__ xg, const u64* __restrict__ whr2,
              const float* __restrict__ fcw, const float* __restrict__ fcb,
              const float* __restrict__ c0, const float* __restrict__ h0,
              float* __restrict__ out)
{
    const int n   = blockIdx.x;
    const int tid = threadIdx.x;
    __shared__ __align__(16) float sh[HID];

    float c = c0[(size_t)n * HID + tid];
    sh[tid] = h0[(size_t)n * HID + tid];
    __syncthreads();

    const int wrp = tid >> 5, lane = tid & 31;

    for (int t = 0; t < TL; t++) {
        const float* xrow = xg + (size_t)(n * TL + t) * 1024;
        u64 ai = pack2(xrow[tid],       0.f);
        u64 aj = pack2(xrow[256 + tid], 0.f);
        u64 af = pack2(xrow[512 + tid], 0.f);
        u64 ao = pack2(xrow[768 + tid], 0.f);

#pragma unroll 4
        for (int k2 = 0; k2 < 128; k2++) {
            const u64 h2 = *(const u64*)(sh + 2 * k2);
            const ulonglong2* wp =
                (const ulonglong2*)(whr2 + ((size_t)k2 * 256 + tid) * 4);
            const ulonglong2 w01 = wp[0];
            const ulonglong2 w23 = wp[1];
            fma2(ai, h2, w01.x);
            fma2(aj, h2, w01.y);
            fma2(af, h2, w23.x);
            fma2(ao, h2, w23.y);
        }
        const float gi = sum2(ai), gj = sum2(aj);
        const float gf = sum2(af), go = sum2(ao);

        const float nc = c * sigmoidf_(gf + 1.f) + sigmoidf_(gi) * tanhf(gj);
        const float nh = tanhf(nc) * sigmoidf_(go);
        c = nc;

        __syncthreads();
        sh[tid] = nh;
        __syncthreads();

        if (wrp < 6) {
#pragma unroll
            for (int cc = 0; cc < 3; cc++) {
                const int col = wrp * 3 + cc;
                float s = 0.f;
#pragma unroll
                for (int k = lane; k < HID; k += 32) s += sh[k] * fcw[(size_t)k * NOUT + col];
#pragma unroll
                for (int off = 16; off; off >>= 1) s += __shfl_down_sync(0xffffffffu, s, off);
                if (lane == 0)
                    out[(size_t)(n * TL + t) * NOUT + col] = s + fcb[col];
            }
        }
    }
}

// ---------------------------------------------------------------------------
// Launch
// ---------------------------------------------------------------------------
extern "C" void kernel_launch(void* const* d_in, const int* in_sizes, int n_in,
                              void* d_out, int out_size)
{
    (void)in_sizes; (void)n_in; (void)out_size;
    const float* inp = (const float*)d_in[0];
    const float* w1  = (const float*)d_in[1];
    const float* b1  = (const float*)d_in[2];
    const float* w2  = (const float*)d_in[3];
    const float* b2  = (const float*)d_in[4];
    const float* w3  = (const float*)d_in[5];
    const float* b3  = (const float*)d_in[6];
    const float* w4  = (const float*)d_in[7];
    const float* b4  = (const float*)d_in[8];
    const float* lw  = (const float*)d_in[9];
    const float* lb  = (const float*)d_in[10];
    const float* fw  = (const float*)d_in[11];
    const float* fb  = (const float*)d_in[12];
    const float* c0  = (const float*)d_in[13];
    const float* h0  = (const float*)d_in[14];
    float* out = (float*)d_out;

    float *c1, *c2, *c3, *c4, *xg;
    u64* whr2;
    cudaGetSymbolAddress((void**)&c1,   g_c1);
    cudaGetSymbolAddress((void**)&c2,   g_c2);
    cudaGetSymbolAddress((void**)&c3,   g_c3);
    cudaGetSymbolAddress((void**)&c4,   g_c4);
    cudaGetSymbolAddress((void**)&xg,   g_xg);
    cudaGetSymbolAddress((void**)&whr2, g_whr2);

    reorder_wh2_k<<<128, 256>>>(lw, whr2);

    // conv stack — TOY=2 row pairing on conv1..3 (weight LDS reuse x2):
    // conv1: 84->42, TOX=4 OXT=11 RP=4 -> 352 thr, grid (6, 2048)  [21 pairs]
    conv1_v6<<<dim3(6, NIMG), 352>>>(inp, w1, b1, c1);
    // conv2: 42->21, TOX=3 OXT=7 RP=4 -> 224 thr, grid (3, 2048)   [11 pairs]
    conv32_v6<42, 42, 21, 21, 0, 3, 7, 4><<<dim3(3, NIMG), 224>>>(c1, w2, b2, c2);
    // conv3: 21->11, TOX=3 OXT=4 RP=6 -> 192 thr, grid (1, 2048)   [6 pairs]
    conv32_v6<21, 21, 11, 11, 1, 3, 4, 6><<<dim3(1, NIMG), 192>>>(c2, w3, b3, c3);
    // conv4 (R8 config): 11->6, TOX=6 OXT=1 ROWS=6 IPB=4 BLK=2, grid (1, 512)
    conv32_v3<11, 11,  6,  6, 1, 6, 1, 6, 4, 2><<<dim3(1, NIMG / 4), 192>>>(c3, w4, b4, c4);

    sgemm_xg_v2<<<dim3(8, 16), 256>>>(c4, lw, lb, xg);
    lstm_fused_v3<<<NT, HID>>>(xg, whr2, fw, fb, c0, h0, out);
}

// round 14
// speedup vs baseline: 1.2580x; 1.0305x over previous
#include <cuda_runtime.h>
#include <math.h>
#include <stdint.h>
#include <string.h>

// ---------------------------------------------------------------------------
// Problem constants
// ---------------------------------------------------------------------------
#define NIMG   2048
#define NT     32
#define TL     64
#define FEAT   1152
#define HID    256
#define NOUT   18

typedef unsigned long long u64;

// ---------------- packed f32x2 helpers (FFMA2: PTX-only pattern) -----------
__device__ __forceinline__ u64 bcast2(float x) {
    u64 d; asm("mov.b64 %0, {%1, %1};" : "=l"(d) : "f"(x)); return d;
}
__device__ __forceinline__ u64 pack2(float a, float b) {
    u64 d; asm("mov.b64 %0, {%1, %2};" : "=l"(d) : "f"(a), "f"(b)); return d;
}
__device__ __forceinline__ float2 unpack2(u64 v) {
    float2 r; asm("mov.b64 {%0, %1}, %2;" : "=f"(r.x), "=f"(r.y) : "l"(v)); return r;
}
__device__ __forceinline__ void fma2(u64& d, u64 a, u64 b) {
    asm("fma.rn.f32x2 %0, %1, %2, %0;" : "+l"(d) : "l"(a), "l"(b));
}
__device__ __forceinline__ float sum2(u64 v) {
    float2 r = unpack2(v); return r.x + r.y;
}

__device__ __forceinline__ float elu_(float v) { return v > 0.f ? v : (__expf(v) - 1.f); }

// ------------------------- device scratch (no cudaMalloc allowed) ----------
__device__ float g_c1[(size_t)NIMG * 42 * 42 * 32];   // 462 MB
__device__ float g_c2[(size_t)NIMG * 21 * 21 * 32];   // 116 MB
__device__ float g_c3[(size_t)NIMG * 11 * 11 * 32];   //  32 MB
__device__ float g_c4[(size_t)NIMG * 6 * 6 * 32];     //   9 MB
__device__ float g_xg[(size_t)NIMG * 1024];           //   8 MB  x@Wx + b
__device__ ulonglong2 g_wij[128 * HID];               // 512 KB (i,j) k-pairs
__device__ ulonglong2 g_wfo[128 * HID];               // 512 KB (f,o) k-pairs

// ---------------------------------------------------------------------------
// Wh reorder, SPLIT layout: each thread's 16B record is lane-contiguous so
// every LDG.128 in the LSTM is a fully-coalesced 512B warp access (4 wf),
// not the 1024B-span/8-wf access of the interleaved 32B-stride layout.
//   wij[k2*256+t] = ( pack2(Wi[2k2][t],Wi[2k2+1][t]), pack2(Wj...) )
//   wfo[k2*256+t] = ( pack2(Wf...), pack2(Wo...) )
// ---------------------------------------------------------------------------
__global__ void reorder_wh3_k(const float* __restrict__ lw,
                              ulonglong2* __restrict__ wij,
                              ulonglong2* __restrict__ wfo)
{
    const int k2 = blockIdx.x;    // 0..127
    const int t  = threadIdx.x;   // 0..255
    const float* r0 = lw + (size_t)(FEAT + 2 * k2) * 1024;
    const float* r1 = lw + (size_t)(FEAT + 2 * k2 + 1) * 1024;
    ulonglong2 vij, vfo;
    vij.x = pack2(r0[t],       r1[t]);         // i pair
    vij.y = pack2(r0[256 + t], r1[256 + t]);   // j pair
    vfo.x = pack2(r0[512 + t], r1[512 + t]);   // f pair
    vfo.y = pack2(r0[768 + t], r1[768 + t]);   // o pair
    wij[(size_t)k2 * 256 + t] = vij;
    wfo[(size_t)k2 * 256 + t] = vfo;
}

// ---------------------------------------------------------------------------
// conv1 v6 (TOY=2, R13 measured-good): Cin=4 -> Cout=32, 84x84 -> 42x42.
// ---------------------------------------------------------------------------
__global__ void __launch_bounds__(352, 2)
conv1_v6(const float* __restrict__ in, const float* __restrict__ w,
         const float* __restrict__ bias, float* __restrict__ out)
{
    __shared__ __align__(16) float sw[9 * 4 * 32];
    const int tid = threadIdx.x;
    if (tid < 288) *(float4*)(sw + tid * 4) = *(const float4*)(w + tid * 4);
    __syncthreads();

    const int cg   = tid & 7;
    const int rest = tid >> 3;
    const int oxg  = rest % 11;
    const int rp   = rest / 11;
    const int pair = blockIdx.x * 4 + rp;
    const int oyA  = 2 * pair;
    const int n    = blockIdx.y;
    const int co0  = cg * 4;
    const int ox0  = oxg * 4;
    if (oyA >= 42) return;
    const bool hasB = (oyA + 1) < 42;

    u64 aAL[4], aAH[4], aBL[4], aBH[4];
    const u64 bL = pack2(bias[co0],     bias[co0 + 1]);
    const u64 bH = pack2(bias[co0 + 2], bias[co0 + 3]);
#pragma unroll
    for (int i = 0; i < 4; i++) { aAL[i] = bL; aAH[i] = bH; aBL[i] = bL; aBH[i] = bH; }

#pragma unroll 1
    for (int ky = 0; ky < 3; ky++) {
        const int iyA = oyA * 2 + ky;
        const int iyB = iyA + 2;
        const bool okA = iyA < 84;
        const bool okB = hasB && iyB < 84;
        if (!okA && !okB) continue;
        const float* inA = in + ((size_t)(n * 84 + iyA) * 84) * 4;
        const float* inB = in + ((size_t)(n * 84 + iyB) * 84) * 4;
#pragma unroll
        for (int kx = 0; kx < 3; kx++) {
            const float* swk = sw + ((ky * 3 + kx) * 4) * 32 + co0;
            const ulonglong2 w0 = *(const ulonglong2*)(swk);
            const ulonglong2 w1 = *(const ulonglong2*)(swk + 32);
            const ulonglong2 w2 = *(const ulonglong2*)(swk + 64);
            const ulonglong2 w3 = *(const ulonglong2*)(swk + 96);
#pragma unroll
            for (int i = 0; i < 4; i++) {
                const int ix = (ox0 + i) * 2 + kx;
                if (ix < 84) {
                    if (okA) {
                        const float4 x = *(const float4*)(inA + (size_t)ix * 4);
                        u64 xb;
                        xb = bcast2(x.x); fma2(aAL[i], xb, w0.x); fma2(aAH[i], xb, w0.y);
                        xb = bcast2(x.y); fma2(aAL[i], xb, w1.x); fma2(aAH[i], xb, w1.y);
                        xb = bcast2(x.z); fma2(aAL[i], xb, w2.x); fma2(aAH[i], xb, w2.y);
                        xb = bcast2(x.w); fma2(aAL[i], xb, w3.x); fma2(aAH[i], xb, w3.y);
                    }
                    if (okB) {
                        const float4 x = *(const float4*)(inB + (size_t)ix * 4);
                        u64 xb;
                        xb = bcast2(x.x); fma2(aBL[i], xb, w0.x); fma2(aBH[i], xb, w0.y);
                        xb = bcast2(x.y); fma2(aBL[i], xb, w1.x); fma2(aBH[i], xb, w1.y);
                        xb = bcast2(x.z); fma2(aBL[i], xb, w2.x); fma2(aBH[i], xb, w2.y);
                        xb = bcast2(x.w); fma2(aBL[i], xb, w3.x); fma2(aBH[i], xb, w3.y);
                    }
                }
            }
        }
    }
    float* outA = out + ((size_t)(n * 42 + oyA) * 42) * 32 + co0;
#pragma unroll
    for (int i = 0; i < 4; i++) {
        const int ox = ox0 + i;
        if (ox < 42) {
            const float2 lo = unpack2(aAL[i]), hi = unpack2(aAH[i]);
            float4 v;
            v.x = elu_(lo.x); v.y = elu_(lo.y); v.z = elu_(hi.x); v.w = elu_(hi.y);
            *(float4*)(outA + (size_t)ox * 32) = v;
        }
    }
    if (hasB) {
        float* outB = out + ((size_t)(n * 42 + oyA + 1) * 42) * 32 + co0;
#pragma unroll
        for (int i = 0; i < 4; i++) {
            const int ox = ox0 + i;
            if (ox < 42) {
                const float2 lo = unpack2(aBL[i]), hi = unpack2(aBH[i]);
                float4 v;
                v.x = elu_(lo.x); v.y = elu_(lo.y); v.z = elu_(hi.x); v.w = elu_(hi.y);
                *(float4*)(outB + (size_t)ox * 32) = v;
            }
        }
    }
}

// ---------------------------------------------------------------------------
// convN v6 (TOY=2, for conv2): two output rows share every weight LDS.
// ---------------------------------------------------------------------------
template <int IH, int IW, int OH, int OW, int PAD, int TOX, int OXT, int RP>
__global__ void __launch_bounds__(8 * OXT * RP, 2)
conv32_v6(const float* __restrict__ in, const float* __restrict__ w,
          const float* __restrict__ bias, float* __restrict__ out)
{
    __shared__ __align__(16) float sw[9 * 32 * 32];
    const int tid = threadIdx.x;
    const int NTH = 8 * OXT * RP;
    for (int i = tid * 4; i < 9 * 32 * 32; i += NTH * 4)
        *(float4*)(sw + i) = *(const float4*)(w + i);
    __syncthreads();

    const int cg   = tid & 7;
    int rest       = tid >> 3;
    const int oxg  = rest % OXT;
    const int rp   = rest / OXT;
    const int pair = blockIdx.x * RP + rp;
    const int oyA  = 2 * pair;
    const int n    = blockIdx.y;
    const int co0  = cg * 4;
    const int ox0  = oxg * TOX;
    if (oyA >= OH) return;
    const bool hasB = (oyA + 1) < OH;

    u64 aAL[TOX], aAH[TOX], aBL[TOX], aBH[TOX];
    const u64 bL = pack2(bias[co0],     bias[co0 + 1]);
    const u64 bH = pack2(bias[co0 + 2], bias[co0 + 3]);
#pragma unroll
    for (int i = 0; i < TOX; i++) { aAL[i] = bL; aAH[i] = bH; aBL[i] = bL; aBH[i] = bH; }

#pragma unroll 1
    for (int ky = 0; ky < 3; ky++) {
        const int iyA = oyA * 2 + ky - PAD;
        const int iyB = iyA + 2;
        const bool okA = (iyA >= 0) && (iyA < IH);
        const bool okB = hasB && (iyB < IH);
        if (!okA && !okB) continue;
        const float* inA = in + ((size_t)(n * IH + iyA) * IW) * 32;
        const float* inB = in + ((size_t)(n * IH + iyB) * IW) * 32;
#pragma unroll
        for (int kx = 0; kx < 3; kx++) {
            const float* swk = sw + ((ky * 3 + kx) * 32) * 32 + co0;
#pragma unroll
            for (int c4 = 0; c4 < 32; c4 += 4) {
                const ulonglong2 w0 = *(const ulonglong2*)(swk + (c4 + 0) * 32);
                const ulonglong2 w1 = *(const ulonglong2*)(swk + (c4 + 1) * 32);
                const ulonglong2 w2 = *(const ulonglong2*)(swk + (c4 + 2) * 32);
                const ulonglong2 w3 = *(const ulonglong2*)(swk + (c4 + 3) * 32);
#pragma unroll
                for (int i = 0; i < TOX; i++) {
                    const int ix = (ox0 + i) * 2 + kx - PAD;
                    if (ix >= 0 && ix < IW) {
                        if (okA) {
                            const float4 x = *(const float4*)(inA + (size_t)ix * 32 + c4);
                            u64 xb;
                            xb = bcast2(x.x); fma2(aAL[i], xb, w0.x); fma2(aAH[i], xb, w0.y);
                            xb = bcast2(x.y); fma2(aAL[i], xb, w1.x); fma2(aAH[i], xb, w1.y);
                            xb = bcast2(x.z); fma2(aAL[i], xb, w2.x); fma2(aAH[i], xb, w2.y);
                            xb = bcast2(x.w); fma2(aAL[i], xb, w3.x); fma2(aAH[i], xb, w3.y);
                        }
                        if (okB) {
                            const float4 x = *(const float4*)(inB + (size_t)ix * 32 + c4);
                            u64 xb;
                            xb = bcast2(x.x); fma2(aBL[i], xb, w0.x); fma2(aBH[i], xb, w0.y);
                            xb = bcast2(x.y); fma2(aBL[i], xb, w1.x); fma2(aBH[i], xb, w1.y);
                            xb = bcast2(x.z); fma2(aBL[i], xb, w2.x); fma2(aBH[i], xb, w2.y);
                            xb = bcast2(x.w); fma2(aBL[i], xb, w3.x); fma2(aBH[i], xb, w3.y);
                        }
                    }
                }
            }
        }
    }
    float* outA = out + ((size_t)(n * OH + oyA) * OW) * 32 + co0;
#pragma unroll
    for (int i = 0; i < TOX; i++) {
        if (ox0 + i < OW) {
            const float2 lo = unpack2(aAL[i]), hi = unpack2(aAH[i]);
            float4 v;
            v.x = elu_(lo.x); v.y = elu_(lo.y); v.z = elu_(hi.x); v.w = elu_(hi.y);
            *(float4*)(outA + (size_t)(ox0 + i) * 32) = v;
        }
    }
    if (hasB) {
        float* outB = out + ((size_t)(n * OH + oyA + 1) * OW) * 32 + co0;
#pragma unroll
        for (int i = 0; i < TOX; i++) {
            if (ox0 + i < OW) {
                const float2 lo = unpack2(aBL[i]), hi = unpack2(aBH[i]);
                float4 v;
                v.x = elu_(lo.x); v.y = elu_(lo.y); v.z = elu_(hi.x); v.w = elu_(hi.y);
                *(float4*)(outB + (size_t)(ox0 + i) * 32) = v;
            }
        }
    }
}

// ---------------------------------------------------------------------------
// convN v3 (single-row, BLK templated) — conv3 (R12 best) + conv4 (R8 best)
// ---------------------------------------------------------------------------
template <int IH, int IW, int OH, int OW, int PAD, int TOX, int OXT, int ROWS,
          int IPB, int BLK>
__global__ void __launch_bounds__(8 * OXT * ROWS * IPB, BLK)
conv32_v3(const float* __restrict__ in, const float* __restrict__ w,
          const float* __restrict__ bias, float* __restrict__ out)
{
    __shared__ __align__(16) float sw[9 * 32 * 32];
    const int tid = threadIdx.x;
    const int NTH = 8 * OXT * ROWS * IPB;
    for (int i = tid * 4; i < 9 * 32 * 32; i += NTH * 4)
        *(float4*)(sw + i) = *(const float4*)(w + i);
    __syncthreads();

    const int cg  = tid & 7;
    int rest      = tid >> 3;
    const int oxg = rest % OXT;  rest /= OXT;
    const int ry  = rest % ROWS;
    const int img = rest / ROWS;
    const int co0 = cg * 4;
    const int ox0 = oxg * TOX;
    const int oy  = blockIdx.x * ROWS + ry;
    const int n   = blockIdx.y * IPB + img;
    if (oy >= OH) return;

    u64 aL[TOX], aH[TOX];
    const u64 bL = pack2(bias[co0],     bias[co0 + 1]);
    const u64 bH = pack2(bias[co0 + 2], bias[co0 + 3]);
#pragma unroll
    for (int i = 0; i < TOX; i++) { aL[i] = bL; aH[i] = bH; }

#pragma unroll 1
    for (int ky = 0; ky < 3; ky++) {
        const int iy = oy * 2 + ky - PAD;
        if (iy < 0 || iy >= IH) continue;
        const float* inr = in + ((size_t)(n * IH + iy) * IW) * 32;
#pragma unroll
        for (int kx = 0; kx < 3; kx++) {
            const float* swk = sw + ((ky * 3 + kx) * 32) * 32 + co0;
#pragma unroll
            for (int c4 = 0; c4 < 32; c4 += 4) {
                const ulonglong2 w0 = *(const ulonglong2*)(swk + (c4 + 0) * 32);
                const ulonglong2 w1 = *(const ulonglong2*)(swk + (c4 + 1) * 32);
                const ulonglong2 w2 = *(const ulonglong2*)(swk + (c4 + 2) * 32);
                const ulonglong2 w3 = *(const ulonglong2*)(swk + (c4 + 3) * 32);
#pragma unroll
                for (int i = 0; i < TOX; i++) {
                    const int ix = (ox0 + i) * 2 + kx - PAD;
                    if (ix >= 0 && ix < IW) {
                        const float4 x = *(const float4*)(inr + (size_t)ix * 32 + c4);
                        u64 xb;
                        xb = bcast2(x.x); fma2(aL[i], xb, w0.x); fma2(aH[i], xb, w0.y);
                        xb = bcast2(x.y); fma2(aL[i], xb, w1.x); fma2(aH[i], xb, w1.y);
                        xb = bcast2(x.z); fma2(aL[i], xb, w2.x); fma2(aH[i], xb, w2.y);
                        xb = bcast2(x.w); fma2(aL[i], xb, w3.x); fma2(aH[i], xb, w3.y);
                    }
                }
            }
        }
    }
    float* outr = out + ((size_t)(n * OH + oy) * OW) * 32 + co0;
#pragma unroll
    for (int i = 0; i < TOX; i++) {
        if (ox0 + i < OW) {
            const float2 lo = unpack2(aL[i]), hi = unpack2(aH[i]);
            float4 v;
            v.x = elu_(lo.x); v.y = elu_(lo.y); v.z = elu_(hi.x); v.w = elu_(hi.y);
            *(float4*)(outr + (size_t)(ox0 + i) * 32) = v;
        }
    }
}

// ---------------------------------------------------------------------------
// SGEMM (unchanged)
// ---------------------------------------------------------------------------
__global__ void __launch_bounds__(256, 2)
sgemm_xg_v2(const float* __restrict__ A, const float* __restrict__ B,
            const float* __restrict__ bias, float* __restrict__ C)
{
    __shared__ __align__(16) float As[8][128];
    __shared__ __align__(16) float Bs[8][128];
    const int bx  = blockIdx.x;
    const int by  = blockIdx.y;
    const int tid = threadIdx.x;
    const int tr  = (tid / 16) * 8;
    const int tc  = (tid % 16) * 8;

    u64 acc[8][4];
#pragma unroll
    for (int i = 0; i < 8; i++)
#pragma unroll
        for (int j = 0; j < 4; j++) acc[i][j] = 0ull;

    const int ar = tid >> 1,  ac = (tid & 1) * 4;
    const int br = tid >> 5,  bc = (tid & 31) * 4;
    const float* Aptr = A + (size_t)(by * 128 + ar) * FEAT + ac;
    const float* Bptr = B + (size_t)br * 1024 + bx * 128 + bc;

    for (int k0 = 0; k0 < FEAT; k0 += 8) {
        const float4 av = *(const float4*)(Aptr + k0);
        As[ac + 0][ar] = av.x; As[ac + 1][ar] = av.y;
        As[ac + 2][ar] = av.z; As[ac + 3][ar] = av.w;
        *(float4*)&Bs[br][bc] = *(const float4*)(Bptr + (size_t)k0 * 1024);
        __syncthreads();
#pragma unroll
        for (int kk = 0; kk < 8; kk++) {
            const float4 a0 = *(const float4*)&As[kk][tr];
            const float4 a1 = *(const float4*)&As[kk][tr + 4];
            const ulonglong2 b0 = *(const ulonglong2*)&Bs[kk][tc];
            const ulonglong2 b1 = *(const ulonglong2*)&Bs[kk][tc + 4];
            const float a[8] = {a0.x, a0.y, a0.z, a0.w, a1.x, a1.y, a1.z, a1.w};
#pragma unroll
            for (int i = 0; i < 8; i++) {
                const u64 ab = bcast2(a[i]);
                fma2(acc[i][0], ab, b0.x);
                fma2(acc[i][1], ab, b0.y);
                fma2(acc[i][2], ab, b1.x);
                fma2(acc[i][3], ab, b1.y);
            }
        }
        __syncthreads();
    }

#pragma unroll
    for (int i = 0; i < 8; i++) {
        const int row = by * 128 + tr + i;
        float* crow = C + (size_t)row * 1024 + bx * 128 + tc;
#pragma unroll
        for (int j = 0; j < 2; j++) {
            const float2 p0 = unpack2(acc[i][j * 2 + 0]);
            const float2 p1 = unpack2(acc[i][j * 2 + 1]);
            float4 v;
            v.x = p0.x + bias[bx * 128 + tc + j * 4 + 0];
            v.y = p0.y + bias[bx * 128 + tc + j * 4 + 1];
            v.z = p1.x + bias[bx * 128 + tc + j * 4 + 2];
            v.w = p1.y + bias[bx * 128 + tc + j * 4 + 3];
            *(float4*)(crow + j * 4) = v;
        }
    }
}

// ---------------------------------------------------------------------------
// Fused LSTM recurrence + FC, v4: split wij/wfo weight arrays so both weight
// LDG.128s per k2 are fully coalesced (512B/warp, 4 wavefronts each) instead
// of spanning 1024B (8 wf) in the interleaved layout. Math order identical.
// ---------------------------------------------------------------------------
__device__ __forceinline__ float sigmoidf_(float x) { return 1.f / (1.f + expf(-x)); }

__global__ void __launch_bounds__(256)
lstm_fused_v4(const float* __restrict__ xg,
              const ulonglong2* __restrict__ wij,
              const ulonglong2* __restrict__ wfo,
              const float* __restrict__ fcw, const float* __restrict__ fcb,
              const float* __restrict__ c0, const float* __restrict__ h0,
              float* __restrict__ out)
{
    const int n   = blockIdx.x;
    const int tid = threadIdx.x;
    __shared__ __align__(16) float sh[HID];

    float c = c0[(size_t)n * HID + tid];
    sh[tid] = h0[(size_t)n * HID + tid];
    __syncthreads();

    const int wrp = tid >> 5, lane = tid & 31;

    for (int t = 0; t < TL; t++) {
        const float* xrow = xg + (size_t)(n * TL + t) * 1024;
        u64 ai = pack2(xrow[tid],       0.f);
        u64 aj = pack2(xrow[256 + tid], 0.f);
        u64 af = pack2(xrow[512 + tid], 0.f);
        u64 ao = pack2(xrow[768 + tid], 0.f);

#pragma unroll 4
        for (int k2 = 0; k2 < 128; k2++) {
            const u64 h2 = *(const u64*)(sh + 2 * k2);
            const ulonglong2 w01 = wij[(size_t)k2 * 256 + tid];
            const ulonglong2 w23 = wfo[(size_t)k2 * 256 + tid];
            fma2(ai, h2, w01.x);
            fma2(aj, h2, w01.y);
            fma2(af, h2, w23.x);
            fma2(ao, h2, w23.y);
        }
        const float gi = sum2(ai), gj = sum2(aj);
        const float gf = sum2(af), go = sum2(ao);

        const float nc = c * sigmoidf_(gf + 1.f) + sigmoidf_(gi) * tanhf(gj);
        const float nh = tanhf(nc) * sigmoidf_(go);
        c = nc;

        __syncthreads();
        sh[tid] = nh;
        __syncthreads();

        if (wrp < 6) {
#pragma unroll
            for (int cc = 0; cc < 3; cc++) {
                const int col = wrp * 3 + cc;
                float s = 0.f;
#pragma unroll
                for (int k = lane; k < HID; k += 32) s += sh[k] * fcw[(size_t)k * NOUT + col];
#pragma unroll
                for (int off = 16; off; off >>= 1) s += __shfl_down_sync(0xffffffffu, s, off);
                if (lane == 0)
                    out[(size_t)(n * TL + t) * NOUT + col] = s + fcb[col];
            }
        }
    }
}

// ---------------------------------------------------------------------------
// Launch
// ---------------------------------------------------------------------------
extern "C" void kernel_launch(void* const* d_in, const int* in_sizes, int n_in,
                              void* d_out, int out_size)
{
    (void)in_sizes; (void)n_in; (void)out_size;
    const float* inp = (const float*)d_in[0];
    const float* w1  = (const float*)d_in[1];
    const float* b1  = (const float*)d_in[2];
    const float* w2  = (const float*)d_in[3];
    const float* b2  = (const float*)d_in[4];
    const float* w3  = (const float*)d_in[5];
    const float* b3  = (const float*)d_in[6];
    const float* w4  = (const float*)d_in[7];
    const float* b4  = (const float*)d_in[8];
    const float* lw  = (const float*)d_in[9];
    const float* lb  = (const float*)d_in[10];
    const float* fw  = (const float*)d_in[11];
    const float* fb  = (const float*)d_in[12];
    const float* c0  = (const float*)d_in[13];
    const float* h0  = (const float*)d_in[14];
    float* out = (float*)d_out;

    float *c1, *c2, *c3, *c4, *xg;
    ulonglong2 *wij, *wfo;
    cudaGetSymbolAddress((void**)&c1,  g_c1);
    cudaGetSymbolAddress((void**)&c2,  g_c2);
    cudaGetSymbolAddress((void**)&c3,  g_c3);
    cudaGetSymbolAddress((void**)&c4,  g_c4);
    cudaGetSymbolAddress((void**)&xg,  g_xg);
    cudaGetSymbolAddress((void**)&wij, g_wij);
    cudaGetSymbolAddress((void**)&wfo, g_wfo);

    reorder_wh3_k<<<128, 256>>>(lw, wij, wfo);

    // conv stack — per-layer measured-best configs:
    // conv1 (R13 v6): TOY=2, TOX=4, 352 thr, grid (6, 2048)
    conv1_v6<<<dim3(6, NIMG), 352>>>(inp, w1, b1, c1);
    // conv2 (R13 v6): TOY=2, TOX=3 OXT=7 RP=4 -> 224 thr, grid (3, 2048)
    conv32_v6<42, 42, 21, 21, 0, 3, 7, 4><<<dim3(3, NIMG), 224>>>(c1, w2, b2, c2);
    // conv3 (R12 v3, 179us): TOX=3 OXT=4 ROWS=6 IPB=1 BLK=3, grid (2, 2048)
    conv32_v3<21, 21, 11, 11, 1, 3, 4, 6, 1, 3><<<dim3(2, NIMG), 192>>>(c2, w3, b3, c3);
    // conv4 (R8 v3): TOX=6 OXT=1 ROWS=6 IPB=4 BLK=2, grid (1, 512)
    conv32_v3<11, 11,  6,  6, 1, 6, 1, 6, 4, 2><<<dim3(1, NIMG / 4), 192>>>(c3, w4, b4, c4);

    sgemm_xg_v2<<<dim3(8, 16), 256>>>(c4, lw, lb, xg);

    // recurrence + FC, coalesced split-weight layout
    lstm_fused_v4<<<NT, HID>>>(xg, wij, wfo, fw, fb, c0, h0, out);
}

// round 15
// speedup vs baseline: 1.3598x; 1.0809x over previous
#include <cuda_runtime.h>
#include <math.h>
#include <stdint.h>
#include <string.h>

// ---------------------------------------------------------------------------
// Problem constants
// ---------------------------------------------------------------------------
#define NIMG   2048
#define NT     32
#define TL     64
#define FEAT   1152
#define HID    256
#define NOUT   18

typedef unsigned long long u64;

// ---------------- packed f32x2 helpers (FFMA2: PTX-only pattern) -----------
__device__ __forceinline__ u64 bcast2(float x) {
    u64 d; asm("mov.b64 %0, {%1, %1};" : "=l"(d) : "f"(x)); return d;
}
__device__ __forceinline__ u64 pack2(float a, float b) {
    u64 d; asm("mov.b64 %0, {%1, %2};" : "=l"(d) : "f"(a), "f"(b)); return d;
}
__device__ __forceinline__ float2 unpack2(u64 v) {
    float2 r; asm("mov.b64 {%0, %1}, %2;" : "=f"(r.x), "=f"(r.y) : "l"(v)); return r;
}
__device__ __forceinline__ void fma2(u64& d, u64 a, u64 b) {
    asm("fma.rn.f32x2 %0, %1, %2, %0;" : "+l"(d) : "l"(a), "l"(b));
}
__device__ __forceinline__ float sum2(u64 v) {
    float2 r = unpack2(v); return r.x + r.y;
}

__device__ __forceinline__ float elu_(float v) { return v > 0.f ? v : (__expf(v) - 1.f); }

// ------------------------- device scratch (no cudaMalloc allowed) ----------
__device__ float g_c1[(size_t)NIMG * 42 * 42 * 32];   // 462 MB
__device__ float g_c2[(size_t)NIMG * 21 * 21 * 32];   // 116 MB
__device__ float g_c3[(size_t)NIMG * 11 * 11 * 32];   //  32 MB
__device__ float g_c4[(size_t)NIMG * 6 * 6 * 32];     //   9 MB
__device__ float g_xg[(size_t)NIMG * 1024];           //   8 MB  x@Wx + b
__device__ ulonglong2 g_wij[128 * HID];               // 512 KB (i,j) k-pairs
__device__ ulonglong2 g_wfo[128 * HID];               // 512 KB (f,o) k-pairs

// ---------------------------------------------------------------------------
// Wh reorder, split coalesced layout (R14, measured-good)
// ---------------------------------------------------------------------------
__global__ void reorder_wh3_k(const float* __restrict__ lw,
                              ulonglong2* __restrict__ wij,
                              ulonglong2* __restrict__ wfo)
{
    const int k2 = blockIdx.x;    // 0..127
    const int t  = threadIdx.x;   // 0..255
    const float* r0 = lw + (size_t)(FEAT + 2 * k2) * 1024;
    const float* r1 = lw + (size_t)(FEAT + 2 * k2 + 1) * 1024;
    ulonglong2 vij, vfo;
    vij.x = pack2(r0[t],       r1[t]);
    vij.y = pack2(r0[256 + t], r1[256 + t]);
    vfo.x = pack2(r0[512 + t], r1[512 + t]);
    vfo.y = pack2(r0[768 + t], r1[768 + t]);
    wij[(size_t)k2 * 256 + t] = vij;
    wfo[(size_t)k2 * 256 + t] = vfo;
}

// ---------------------------------------------------------------------------
// conv1 v5 (ci-pair, R10 verbatim): Cin=4 -> Cout=32, 84x84 -> 42x42.
// acc[co] = (even-ci, odd-ci) pair; input ulonglong2 = two natural ci-pairs,
// zero broadcast movs: 9 instr / 16 MACs vs 13 for the bcast form.
// ---------------------------------------------------------------------------
__global__ void __launch_bounds__(352, 2)
conv1_v5(const float* __restrict__ in, const float* __restrict__ w,
         const float* __restrict__ bias, float* __restrict__ out)
{
    __shared__ __align__(16) u64 sw2[9 * 2 * 32];     // [kpos][p][co] pairs
    const int tid = threadIdx.x;
    for (int i = tid; i < 9 * 2 * 32; i += 352) {
        const int kpos = i >> 6, p = (i >> 5) & 1, co = i & 31;
        sw2[i] = pack2(w[(kpos * 4 + 2 * p) * 32 + co],
                       w[(kpos * 4 + 2 * p + 1) * 32 + co]);
    }
    __syncthreads();

    const int cg   = tid & 7;
    const int rest = tid >> 3;
    const int oxg  = rest % 11;
    const int ry   = rest / 11;
    const int oy   = blockIdx.x * 4 + ry;
    const int n    = blockIdx.y;
    const int co0  = cg * 4;
    const int ox0  = oxg * 4;
    if (oy >= 42) return;

    u64 acc[4][4];
#pragma unroll
    for (int i = 0; i < 4; i++)
#pragma unroll
        for (int c = 0; c < 4; c++) acc[i][c] = 0ull;

#pragma unroll 1
    for (int ky = 0; ky < 3; ky++) {
        const int iy = oy * 2 + ky;
        if (iy >= 84) continue;
        const float* inr = in + ((size_t)(n * 84 + iy) * 84) * 4;
#pragma unroll
        for (int kx = 0; kx < 3; kx++) {
            const u64* swk = sw2 + (ky * 3 + kx) * 2 * 32;
            const ulonglong2 wa01 = *(const ulonglong2*)(swk + co0);
            const ulonglong2 wa23 = *(const ulonglong2*)(swk + co0 + 2);
            const ulonglong2 wb01 = *(const ulonglong2*)(swk + 32 + co0);
            const ulonglong2 wb23 = *(const ulonglong2*)(swk + 32 + co0 + 2);
#pragma unroll
            for (int i = 0; i < 4; i++) {
                const int ix = (ox0 + i) * 2 + kx;
                if (ix < 84) {
                    const ulonglong2 xv = *(const ulonglong2*)(inr + (size_t)ix * 4);
                    fma2(acc[i][0], xv.x, wa01.x);
                    fma2(acc[i][1], xv.x, wa01.y);
                    fma2(acc[i][2], xv.x, wa23.x);
                    fma2(acc[i][3], xv.x, wa23.y);
                    fma2(acc[i][0], xv.y, wb01.x);
                    fma2(acc[i][1], xv.y, wb01.y);
                    fma2(acc[i][2], xv.y, wb23.x);
                    fma2(acc[i][3], xv.y, wb23.y);
                }
            }
        }
    }
    const float4 bv = *(const float4*)(bias + co0);
    float* outr = out + ((size_t)(n * 42 + oy) * 42) * 32 + co0;
#pragma unroll
    for (int i = 0; i < 4; i++) {
        const int ox = ox0 + i;
        if (ox < 42) {
            float4 v;
            v.x = elu_(sum2(acc[i][0]) + bv.x);
            v.y = elu_(sum2(acc[i][1]) + bv.y);
            v.z = elu_(sum2(acc[i][2]) + bv.z);
            v.w = elu_(sum2(acc[i][3]) + bv.w);
            *(float4*)(outr + (size_t)ox * 32) = v;
        }
    }
}

// ---------------------------------------------------------------------------
// convN v6 (TOY=2, for conv2 — R13/R14 measured-good)
// ---------------------------------------------------------------------------
template <int IH, int IW, int OH, int OW, int PAD, int TOX, int OXT, int RP>
__global__ void __launch_bounds__(8 * OXT * RP, 2)
conv32_v6(const float* __restrict__ in, const float* __restrict__ w,
          const float* __restrict__ bias, float* __restrict__ out)
{
    __shared__ __align__(16) float sw[9 * 32 * 32];
    const int tid = threadIdx.x;
    const int NTH = 8 * OXT * RP;
    for (int i = tid * 4; i < 9 * 32 * 32; i += NTH * 4)
        *(float4*)(sw + i) = *(const float4*)(w + i);
    __syncthreads();

    const int cg   = tid & 7;
    int rest       = tid >> 3;
    const int oxg  = rest % OXT;
    const int rp   = rest / OXT;
    const int pair = blockIdx.x * RP + rp;
    const int oyA  = 2 * pair;
    const int n    = blockIdx.y;
    const int co0  = cg * 4;
    const int ox0  = oxg * TOX;
    if (oyA >= OH) return;
    const bool hasB = (oyA + 1) < OH;

    u64 aAL[TOX], aAH[TOX], aBL[TOX], aBH[TOX];
    const u64 bL = pack2(bias[co0],     bias[co0 + 1]);
    const u64 bH = pack2(bias[co0 + 2], bias[co0 + 3]);
#pragma unroll
    for (int i = 0; i < TOX; i++) { aAL[i] = bL; aAH[i] = bH; aBL[i] = bL; aBH[i] = bH; }

#pragma unroll 1
    for (int ky = 0; ky < 3; ky++) {
        const int iyA = oyA * 2 + ky - PAD;
        const int iyB = iyA + 2;
        const bool okA = (iyA >= 0) && (iyA < IH);
        const bool okB = hasB && (iyB < IH);
        if (!okA && !okB) continue;
        const float* inA = in + ((size_t)(n * IH + iyA) * IW) * 32;
        const float* inB = in + ((size_t)(n * IH + iyB) * IW) * 32;
#pragma unroll
        for (int kx = 0; kx < 3; kx++) {
            const float* swk = sw + ((ky * 3 + kx) * 32) * 32 + co0;
#pragma unroll
            for (int c4 = 0; c4 < 32; c4 += 4) {
                const ulonglong2 w0 = *(const ulonglong2*)(swk + (c4 + 0) * 32);
                const ulonglong2 w1 = *(const ulonglong2*)(swk + (c4 + 1) * 32);
                const ulonglong2 w2 = *(const ulonglong2*)(swk + (c4 + 2) * 32);
                const ulonglong2 w3 = *(const ulonglong2*)(swk + (c4 + 3) * 32);
#pragma unroll
                for (int i = 0; i < TOX; i++) {
                    const int ix = (ox0 + i) * 2 + kx - PAD;
                    if (ix >= 0 && ix < IW) {
                        if (okA) {
                            const float4 x = *(const float4*)(inA + (size_t)ix * 32 + c4);
                            u64 xb;
                            xb = bcast2(x.x); fma2(aAL[i], xb, w0.x); fma2(aAH[i], xb, w0.y);
                            xb = bcast2(x.y); fma2(aAL[i], xb, w1.x); fma2(aAH[i], xb, w1.y);
                            xb = bcast2(x.z); fma2(aAL[i], xb, w2.x); fma2(aAH[i], xb, w2.y);
                            xb = bcast2(x.w); fma2(aAL[i], xb, w3.x); fma2(aAH[i], xb, w3.y);
                        }
                        if (okB) {
                            const float4 x = *(const float4*)(inB + (size_t)ix * 32 + c4);
                            u64 xb;
                            xb = bcast2(x.x); fma2(aBL[i], xb, w0.x); fma2(aBH[i], xb, w0.y);
                            xb = bcast2(x.y); fma2(aBL[i], xb, w1.x); fma2(aBH[i], xb, w1.y);
                            xb = bcast2(x.z); fma2(aBL[i], xb, w2.x); fma2(aBH[i], xb, w2.y);
                            xb = bcast2(x.w); fma2(aBL[i], xb, w3.x); fma2(aBH[i], xb, w3.y);
                        }
                    }
                }
            }
        }
    }
    float* outA = out + ((size_t)(n * OH + oyA) * OW) * 32 + co0;
#pragma unroll
    for (int i = 0; i < TOX; i++) {
        if (ox0 + i < OW) {
            const float2 lo = unpack2(aAL[i]), hi = unpack2(aAH[i]);
            float4 v;
            v.x = elu_(lo.x); v.y = elu_(lo.y); v.z = elu_(hi.x); v.w = elu_(hi.y);
            *(float4*)(outA + (size_t)(ox0 + i) * 32) = v;
        }
    }
    if (hasB) {
        float* outB = out + ((size_t)(n * OH + oyA + 1) * OW) * 32 + co0;
#pragma unroll
        for (int i = 0; i < TOX; i++) {
            if (ox0 + i < OW) {
                const float2 lo = unpack2(aBL[i]), hi = unpack2(aBH[i]);
                float4 v;
                v.x = elu_(lo.x); v.y = elu_(lo.y); v.z = elu_(hi.x); v.w = elu_(hi.y);
                *(float4*)(outB + (size_t)(ox0 + i) * 32) = v;
            }
        }
    }
}

// ---------------------------------------------------------------------------
// convN v3 (single-row, BLK templated) — conv3 (R12 best) + conv4 (R8 best)
// ---------------------------------------------------------------------------
template <int IH, int IW, int OH, int OW, int PAD, int TOX, int OXT, int ROWS,
          int IPB, int BLK>
__global__ void __launch_bounds__(8 * OXT * ROWS * IPB, BLK)
conv32_v3(const float* __restrict__ in, const float* __restrict__ w,
          const float* __restrict__ bias, float* __restrict__ out)
{
    __shared__ __align__(16) float sw[9 * 32 * 32];
    const int tid = threadIdx.x;
    const int NTH = 8 * OXT * ROWS * IPB;
    for (int i = tid * 4; i < 9 * 32 * 32; i += NTH * 4)
        *(float4*)(sw + i) = *(const float4*)(w + i);
    __syncthreads();

    const int cg  = tid & 7;
    int rest      = tid >> 3;
    const int oxg = rest % OXT;  rest /= OXT;
    const int ry  = rest % ROWS;
    const int img = rest / ROWS;
    const int co0 = cg * 4;
    const int ox0 = oxg * TOX;
    const int oy  = blockIdx.x * ROWS + ry;
    const int n   = blockIdx.y * IPB + img;
    if (oy >= OH) return;

    u64 aL[TOX], aH[TOX];
    const u64 bL = pack2(bias[co0],     bias[co0 + 1]);
    const u64 bH = pack2(bias[co0 + 2], bias[co0 + 3]);
#pragma unroll
    for (int i = 0; i < TOX; i++) { aL[i] = bL; aH[i] = bH; }

#pragma unroll 1
    for (int ky = 0; ky < 3; ky++) {
        const int iy = oy * 2 + ky - PAD;
        if (iy < 0 || iy >= IH) continue;
        const float* inr = in + ((size_t)(n * IH + iy) * IW) * 32;
#pragma unroll
        for (int kx = 0; kx < 3; kx++) {
            const float* swk = sw + ((ky * 3 + kx) * 32) * 32 + co0;
#pragma unroll
            for (int c4 = 0; c4 < 32; c4 += 4) {
                const ulonglong2 w0 = *(const ulonglong2*)(swk + (c4 + 0) * 32);
                const ulonglong2 w1 = *(const ulonglong2*)(swk + (c4 + 1) * 32);
                const ulonglong2 w2 = *(const ulonglong2*)(swk + (c4 + 2) * 32);
                const ulonglong2 w3 = *(const ulonglong2*)(swk + (c4 + 3) * 32);
#pragma unroll
                for (int i = 0; i < TOX; i++) {
                    const int ix = (ox0 + i) * 2 + kx - PAD;
                    if (ix >= 0 && ix < IW) {
                        const float4 x = *(const float4*)(inr + (size_t)ix * 32 + c4);
                        u64 xb;
                        xb = bcast2(x.x); fma2(aL[i], xb, w0.x); fma2(aH[i], xb, w0.y);
                        xb = bcast2(x.y); fma2(aL[i], xb, w1.x); fma2(aH[i], xb, w1.y);
                        xb = bcast2(x.z); fma2(aL[i], xb, w2.x); fma2(aH[i], xb, w2.y);
                        xb = bcast2(x.w); fma2(aL[i], xb, w3.x); fma2(aH[i], xb, w3.y);
                    }
                }
            }
        }
    }
    float* outr = out + ((size_t)(n * OH + oy) * OW) * 32 + co0;
#pragma unroll
    for (int i = 0; i < TOX; i++) {
        if (ox0 + i < OW) {
            const float2 lo = unpack2(aL[i]), hi = unpack2(aH[i]);
            float4 v;
            v.x = elu_(lo.x); v.y = elu_(lo.y); v.z = elu_(hi.x); v.w = elu_(hi.y);
            *(float4*)(outr + (size_t)(ox0 + i) * 32) = v;
        }
    }
}

// ---------------------------------------------------------------------------
// SGEMM (unchanged)
// ---------------------------------------------------------------------------
__global__ void __launch_bounds__(256, 2)
sgemm_xg_v2(const float* __restrict__ A, const float* __restrict__ B,
            const float* __restrict__ bias, float* __restrict__ C)
{
    __shared__ __align__(16) float As[8][128];
    __shared__ __align__(16) float Bs[8][128];
    const int bx  = blockIdx.x;
    const int by  = blockIdx.y;
    const int tid = threadIdx.x;
    const int tr  = (tid / 16) * 8;
    const int tc  = (tid % 16) * 8;

    u64 acc[8][4];
#pragma unroll
    for (int i = 0; i < 8; i++)
#pragma unroll
        for (int j = 0; j < 4; j++) acc[i][j] = 0ull;

    const int ar = tid >> 1,  ac = (tid & 1) * 4;
    const int br = tid >> 5,  bc = (tid & 31) * 4;
    const float* Aptr = A + (size_t)(by * 128 + ar) * FEAT + ac;
    const float* Bptr = B + (size_t)br * 1024 + bx * 128 + bc;

    for (int k0 = 0; k0 < FEAT; k0 += 8) {
        const float4 av = *(const float4*)(Aptr + k0);
        As[ac + 0][ar] = av.x; As[ac + 1][ar] = av.y;
        As[ac + 2][ar] = av.z; As[ac + 3][ar] = av.w;
        *(float4*)&Bs[br][bc] = *(const float4*)(Bptr + (size_t)k0 * 1024);
        __syncthreads();
#pragma unroll
        for (int kk = 0; kk < 8; kk++) {
            const float4 a0 = *(const float4*)&As[kk][tr];
            const float4 a1 = *(const float4*)&As[kk][tr + 4];
            const ulonglong2 b0 = *(const ulonglong2*)&Bs[kk][tc];
            const ulonglong2 b1 = *(const ulonglong2*)&Bs[kk][tc + 4];
            const float a[8] = {a0.x, a0.y, a0.z, a0.w, a1.x, a1.y, a1.z, a1.w};
#pragma unroll
            for (int i = 0; i < 8; i++) {
                const u64 ab = bcast2(a[i]);
                fma2(acc[i][0], ab, b0.x);
                fma2(acc[i][1], ab, b0.y);
                fma2(acc[i][2], ab, b1.x);
                fma2(acc[i][3], ab, b1.y);
            }
        }
        __syncthreads();
    }

#pragma unroll
    for (int i = 0; i < 8; i++) {
        const int row = by * 128 + tr + i;
        float* crow = C + (size_t)row * 1024 + bx * 128 + tc;
#pragma unroll
        for (int j = 0; j < 2; j++) {
            const float2 p0 = unpack2(acc[i][j * 2 + 0]);
            const float2 p1 = unpack2(acc[i][j * 2 + 1]);
            float4 v;
            v.x = p0.x + bias[bx * 128 + tc + j * 4 + 0];
            v.y = p0.y + bias[bx * 128 + tc + j * 4 + 1];
            v.z = p1.x + bias[bx * 128 + tc + j * 4 + 2];
            v.w = p1.y + bias[bx * 128 + tc + j * 4 + 3];
            *(float4*)(crow + j * 4) = v;
        }
    }
}

// ---------------------------------------------------------------------------
// LSTM v5: 2-CTA cluster per trajectory. CTA rank r owns hidden [128r,128r+128).
// Per-SM weight traffic halves (0.5 MB/step) vs the 1-CTA version. h is
// exchanged per step via DSMEM store + one cluster barrier; sh is
// double-buffered so one sync per step suffices.
// ---------------------------------------------------------------------------
__device__ __forceinline__ float sigmoidf_(float x) { return 1.f / (1.f + expf(-x)); }

__global__ void __launch_bounds__(128) __cluster_dims__(2, 1, 1)
lstm_cluster_v5(const float* __restrict__ xg,
                const ulonglong2* __restrict__ wij,
                const ulonglong2* __restrict__ wfo,
                const float* __restrict__ fcw, const float* __restrict__ fcb,
                const float* __restrict__ c0, const float* __restrict__ h0,
                float* __restrict__ out)
{
    const int n   = blockIdx.x >> 1;     // trajectory
    const int tid = threadIdx.x;         // 0..127
    uint32_t rank;
    asm("mov.u32 %0, %%cluster_ctarank;" : "=r"(rank));
    const int tg = (int)rank * 128 + tid;  // global hidden index

    __shared__ __align__(16) float sh[2][HID];

    float c = c0[(size_t)n * HID + tg];
    sh[0][tid]       = h0[(size_t)n * HID + tid];
    sh[0][128 + tid] = h0[(size_t)n * HID + 128 + tid];
    __syncthreads();
    // ensure peer CTA is initialized before any DSMEM traffic
    asm volatile("barrier.cluster.arrive.aligned;" ::: "memory");
    asm volatile("barrier.cluster.wait.aligned;" ::: "memory");

    // precompute peer address of sh (same local offset, peer rank)
    const uint32_t peer = rank ^ 1u;
    const int wrp = tid >> 5, lane = tid & 31;

    for (int t = 0; t < TL; t++) {
        const int p = t & 1, q = p ^ 1;
        const float* xrow = xg + (size_t)(n * TL + t) * 1024;
        u64 ai = pack2(xrow[tg],       0.f);
        u64 aj = pack2(xrow[256 + tg], 0.f);
        u64 af = pack2(xrow[512 + tg], 0.f);
        u64 ao = pack2(xrow[768 + tg], 0.f);

#pragma unroll 4
        for (int k2 = 0; k2 < 128; k2++) {
            const u64 h2 = *(const u64*)(&sh[p][2 * k2]);
            const ulonglong2 w01 = wij[(size_t)k2 * 256 + tg];
            const ulonglong2 w23 = wfo[(size_t)k2 * 256 + tg];
            fma2(ai, h2, w01.x);
            fma2(aj, h2, w01.y);
            fma2(af, h2, w23.x);
            fma2(ao, h2, w23.y);
        }
        const float gi = sum2(ai), gj = sum2(aj);
        const float gf = sum2(af), go = sum2(ao);

        const float nc = c * sigmoidf_(gf + 1.f) + sigmoidf_(gi) * tanhf(gj);
        const float nh = tanhf(nc) * sigmoidf_(go);
        c = nc;

        // publish nh: local + peer smem (same offset) via DSMEM
        sh[q][tg] = nh;
        {
            uint32_t laddr = (uint32_t)__cvta_generic_to_shared(&sh[q][tg]);
            uint32_t raddr;
            asm("mapa.shared::cluster.u32 %0, %1, %2;"
                : "=r"(raddr) : "r"(laddr), "r"(peer));
            asm volatile("st.shared::cluster.f32 [%0], %1;"
                         :: "r"(raddr), "f"(nh) : "memory");
        }
        // one cluster-wide barrier per step (orders DSMEM writes, acts as
        // block barrier too since all threads participate)
        asm volatile("barrier.cluster.arrive.aligned;" ::: "memory");
        asm volatile("barrier.cluster.wait.aligned;" ::: "memory");

        // FC head: CTA rank r covers cols [9r, 9r+9); warps 0..2, 3 cols each
        if (wrp < 3) {
#pragma unroll
            for (int cc = 0; cc < 3; cc++) {
                const int col = (int)rank * 9 + wrp * 3 + cc;
                float s = 0.f;
#pragma unroll
                for (int k = lane; k < HID; k += 32) s += sh[q][k] * fcw[(size_t)k * NOUT + col];
#pragma unroll
                for (int off = 16; off; off >>= 1) s += __shfl_down_sync(0xffffffffu, s, off);
                if (lane == 0)
                    out[(size_t)(n * TL + t) * NOUT + col] = s + fcb[col];
            }
        }
    }
}

// ---------------------------------------------------------------------------
// Launch
// ---------------------------------------------------------------------------
extern "C" void kernel_launch(void* const* d_in, const int* in_sizes, int n_in,
                              void* d_out, int out_size)
{
    (void)in_sizes; (void)n_in; (void)out_size;
    const float* inp = (const float*)d_in[0];
    const float* w1  = (const float*)d_in[1];
    const float* b1  = (const float*)d_in[2];
    const float* w2  = (const float*)d_in[3];
    const float* b2  = (const float*)d_in[4];
    const float* w3  = (const float*)d_in[5];
    const float* b3  = (const float*)d_in[6];
    const float* w4  = (const float*)d_in[7];
    const float* b4  = (const float*)d_in[8];
    const float* lw  = (const float*)d_in[9];
    const float* lb  = (const float*)d_in[10];
    const float* fw  = (const float*)d_in[11];
    const float* fb  = (const float*)d_in[12];
    const float* c0  = (const float*)d_in[13];
    const float* h0  = (const float*)d_in[14];
    float* out = (float*)d_out;

    float *c1, *c2, *c3, *c4, *xg;
    ulonglong2 *wij, *wfo;
    cudaGetSymbolAddress((void**)&c1,  g_c1);
    cudaGetSymbolAddress((void**)&c2,  g_c2);
    cudaGetSymbolAddress((void**)&c3,  g_c3);
    cudaGetSymbolAddress((void**)&c4,  g_c4);
    cudaGetSymbolAddress((void**)&xg,  g_xg);
    cudaGetSymbolAddress((void**)&wij, g_wij);
    cudaGetSymbolAddress((void**)&wfo, g_wfo);

    reorder_wh3_k<<<128, 256>>>(lw, wij, wfo);

    // conv stack — per-layer measured-best configs:
    // conv1 (R10 v5 ci-pair): TOX=4, 352 thr, grid (11, 2048)
    conv1_v5<<<dim3(11, NIMG), 352>>>(inp, w1, b1, c1);
    // conv2 (R13 v6): TOY=2, TOX=3 OXT=7 RP=4 -> 224 thr, grid (3, 2048)
    conv32_v6<42, 42, 21, 21, 0, 3, 7, 4><<<dim3(3, NIMG), 224>>>(c1, w2, b2, c2);
    // conv3 (R12 v3, 179us): TOX=3 OXT=4 ROWS=6 IPB=1 BLK=3, grid (2, 2048)
    conv32_v3<21, 21, 11, 11, 1, 3, 4, 6, 1, 3><<<dim3(2, NIMG), 192>>>(c2, w3, b3, c3);
    // conv4 (R8 v3): TOX=6 OXT=1 ROWS=6 IPB=4 BLK=2, grid (1, 512)
    conv32_v3<11, 11,  6,  6, 1, 6, 1, 6, 4, 2><<<dim3(1, NIMG / 4), 192>>>(c3, w4, b4, c4);

    sgemm_xg_v2<<<dim3(8, 16), 256>>>(c4, lw, lb, xg);

    // recurrence + FC: 2-CTA cluster per trajectory (64 CTAs / 64 SMs)
    lstm_cluster_v5<<<NT * 2, 128>>>(xg, wij, wfo, fw, fb, c0, h0, out);
}

// round 16
// speedup vs baseline: 1.6147x; 1.1874x over previous
#include <cuda_runtime.h>
#include <math.h>
#include <stdint.h>
#include <string.h>

// ---------------------------------------------------------------------------
// Problem constants
// ---------------------------------------------------------------------------
#define NIMG   2048
#define NT     32
#define TL     64
#define FEAT   1152
#define HID    256
#define NOUT   18

typedef unsigned long long u64;

// ---------------- packed f32x2 helpers (FFMA2: PTX-only pattern) -----------
__device__ __forceinline__ u64 bcast2(float x) {
    u64 d; asm("mov.b64 %0, {%1, %1};" : "=l"(d) : "f"(x)); return d;
}
__device__ __forceinline__ u64 pack2(float a, float b) {
    u64 d; asm("mov.b64 %0, {%1, %2};" : "=l"(d) : "f"(a), "f"(b)); return d;
}
__device__ __forceinline__ float2 unpack2(u64 v) {
    float2 r; asm("mov.b64 {%0, %1}, %2;" : "=f"(r.x), "=f"(r.y) : "l"(v)); return r;
}
__device__ __forceinline__ void fma2(u64& d, u64 a, u64 b) {
    asm("fma.rn.f32x2 %0, %1, %2, %0;" : "+l"(d) : "l"(a), "l"(b));
}
__device__ __forceinline__ float sum2(u64 v) {
    float2 r = unpack2(v); return r.x + r.y;
}

__device__ __forceinline__ float elu_(float v) { return v > 0.f ? v : (__expf(v) - 1.f); }

// ------------------------- device scratch (no cudaMalloc allowed) ----------
__device__ float g_c1[(size_t)NIMG * 42 * 42 * 32];   // 462 MB
__device__ float g_c2[(size_t)NIMG * 21 * 21 * 32];   // 116 MB
__device__ float g_c3[(size_t)NIMG * 11 * 11 * 32];   //  32 MB
__device__ float g_c4[(size_t)NIMG * 6 * 6 * 32];     //   9 MB
__device__ float g_xg[(size_t)NIMG * 1024];           //   8 MB  x@Wx + b
__device__ ulonglong2 g_wij[128 * HID];               // 512 KB (i,j) k-pairs
__device__ ulonglong2 g_wfo[128 * HID];               // 512 KB (f,o) k-pairs

// ---------------------------------------------------------------------------
// Wh reorder, split coalesced layout (R14, measured-good)
// ---------------------------------------------------------------------------
__global__ void reorder_wh3_k(const float* __restrict__ lw,
                              ulonglong2* __restrict__ wij,
                              ulonglong2* __restrict__ wfo)
{
    const int k2 = blockIdx.x;    // 0..127
    const int t  = threadIdx.x;   // 0..255
    const float* r0 = lw + (size_t)(FEAT + 2 * k2) * 1024;
    const float* r1 = lw + (size_t)(FEAT + 2 * k2 + 1) * 1024;
    ulonglong2 vij, vfo;
    vij.x = pack2(r0[t],       r1[t]);
    vij.y = pack2(r0[256 + t], r1[256 + t]);
    vfo.x = pack2(r0[512 + t], r1[512 + t]);
    vfo.y = pack2(r0[768 + t], r1[768 + t]);
    wij[(size_t)k2 * 256 + t] = vij;
    wfo[(size_t)k2 * 256 + t] = vfo;
}

// ---------------------------------------------------------------------------
// conv1 v5 (ci-pair, R15 measured-good): Cin=4 -> Cout=32, 84x84 -> 42x42.
// ---------------------------------------------------------------------------
__global__ void __launch_bounds__(352, 2)
conv1_v5(const float* __restrict__ in, const float* __restrict__ w,
         const float* __restrict__ bias, float* __restrict__ out)
{
    __shared__ __align__(16) u64 sw2[9 * 2 * 32];     // [kpos][p][co] pairs
    const int tid = threadIdx.x;
    for (int i = tid; i < 9 * 2 * 32; i += 352) {
        const int kpos = i >> 6, p = (i >> 5) & 1, co = i & 31;
        sw2[i] = pack2(w[(kpos * 4 + 2 * p) * 32 + co],
                       w[(kpos * 4 + 2 * p + 1) * 32 + co]);
    }
    __syncthreads();

    const int cg   = tid & 7;
    const int rest = tid >> 3;
    const int oxg  = rest % 11;
    const int ry   = rest / 11;
    const int oy   = blockIdx.x * 4 + ry;
    const int n    = blockIdx.y;
    const int co0  = cg * 4;
    const int ox0  = oxg * 4;
    if (oy >= 42) return;

    u64 acc[4][4];
#pragma unroll
    for (int i = 0; i < 4; i++)
#pragma unroll
        for (int c = 0; c < 4; c++) acc[i][c] = 0ull;

#pragma unroll 1
    for (int ky = 0; ky < 3; ky++) {
        const int iy = oy * 2 + ky;
        if (iy >= 84) continue;
        const float* inr = in + ((size_t)(n * 84 + iy) * 84) * 4;
#pragma unroll
        for (int kx = 0; kx < 3; kx++) {
            const u64* swk = sw2 + (ky * 3 + kx) * 2 * 32;
            const ulonglong2 wa01 = *(const ulonglong2*)(swk + co0);
            const ulonglong2 wa23 = *(const ulonglong2*)(swk + co0 + 2);
            const ulonglong2 wb01 = *(const ulonglong2*)(swk + 32 + co0);
            const ulonglong2 wb23 = *(const ulonglong2*)(swk + 32 + co0 + 2);
#pragma unroll
            for (int i = 0; i < 4; i++) {
                const int ix = (ox0 + i) * 2 + kx;
                if (ix < 84) {
                    const ulonglong2 xv = *(const ulonglong2*)(inr + (size_t)ix * 4);
                    fma2(acc[i][0], xv.x, wa01.x);
                    fma2(acc[i][1], xv.x, wa01.y);
                    fma2(acc[i][2], xv.x, wa23.x);
                    fma2(acc[i][3], xv.x, wa23.y);
                    fma2(acc[i][0], xv.y, wb01.x);
                    fma2(acc[i][1], xv.y, wb01.y);
                    fma2(acc[i][2], xv.y, wb23.x);
                    fma2(acc[i][3], xv.y, wb23.y);
                }
            }
        }
    }
    const float4 bv = *(const float4*)(bias + co0);
    float* outr = out + ((size_t)(n * 42 + oy) * 42) * 32 + co0;
#pragma unroll
    for (int i = 0; i < 4; i++) {
        const int ox = ox0 + i;
        if (ox < 42) {
            float4 v;
            v.x = elu_(sum2(acc[i][0]) + bv.x);
            v.y = elu_(sum2(acc[i][1]) + bv.y);
            v.z = elu_(sum2(acc[i][2]) + bv.z);
            v.w = elu_(sum2(acc[i][3]) + bv.w);
            *(float4*)(outr + (size_t)ox * 32) = v;
        }
    }
}

// ---------------------------------------------------------------------------
// convN v6 (TOY=2, for conv2 — R13/R15 measured-good)
// ---------------------------------------------------------------------------
template <int IH, int IW, int OH, int OW, int PAD, int TOX, int OXT, int RP>
__global__ void __launch_bounds__(8 * OXT * RP, 2)
conv32_v6(const float* __restrict__ in, const float* __restrict__ w,
          const float* __restrict__ bias, float* __restrict__ out)
{
    __shared__ __align__(16) float sw[9 * 32 * 32];
    const int tid = threadIdx.x;
    const int NTH = 8 * OXT * RP;
    for (int i = tid * 4; i < 9 * 32 * 32; i += NTH * 4)
        *(float4*)(sw + i) = *(const float4*)(w + i);
    __syncthreads();

    const int cg   = tid & 7;
    int rest       = tid >> 3;
    const int oxg  = rest % OXT;
    const int rp   = rest / OXT;
    const int pair = blockIdx.x * RP + rp;
    const int oyA  = 2 * pair;
    const int n    = blockIdx.y;
    const int co0  = cg * 4;
    const int ox0  = oxg * TOX;
    if (oyA >= OH) return;
    const bool hasB = (oyA + 1) < OH;

    u64 aAL[TOX], aAH[TOX], aBL[TOX], aBH[TOX];
    const u64 bL = pack2(bias[co0],     bias[co0 + 1]);
    const u64 bH = pack2(bias[co0 + 2], bias[co0 + 3]);
#pragma unroll
    for (int i = 0; i < TOX; i++) { aAL[i] = bL; aAH[i] = bH; aBL[i] = bL; aBH[i] = bH; }

#pragma unroll 1
    for (int ky = 0; ky < 3; ky++) {
        const int iyA = oyA * 2 + ky - PAD;
        const int iyB = iyA + 2;
        const bool okA = (iyA >= 0) && (iyA < IH);
        const bool okB = hasB && (iyB < IH);
        if (!okA && !okB) continue;
        const float* inA = in + ((size_t)(n * IH + iyA) * IW) * 32;
        const float* inB = in + ((size_t)(n * IH + iyB) * IW) * 32;
#pragma unroll
        for (int kx = 0; kx < 3; kx++) {
            const float* swk = sw + ((ky * 3 + kx) * 32) * 32 + co0;
#pragma unroll
            for (int c4 = 0; c4 < 32; c4 += 4) {
                const ulonglong2 w0 = *(const ulonglong2*)(swk + (c4 + 0) * 32);
                const ulonglong2 w1 = *(const ulonglong2*)(swk + (c4 + 1) * 32);
                const ulonglong2 w2 = *(const ulonglong2*)(swk + (c4 + 2) * 32);
                const ulonglong2 w3 = *(const ulonglong2*)(swk + (c4 + 3) * 32);
#pragma unroll
                for (int i = 0; i < TOX; i++) {
                    const int ix = (ox0 + i) * 2 + kx - PAD;
                    if (ix >= 0 && ix < IW) {
                        if (okA) {
                            const float4 x = *(const float4*)(inA + (size_t)ix * 32 + c4);
                            u64 xb;
                            xb = bcast2(x.x); fma2(aAL[i], xb, w0.x); fma2(aAH[i], xb, w0.y);
                            xb = bcast2(x.y); fma2(aAL[i], xb, w1.x); fma2(aAH[i], xb, w1.y);
                            xb = bcast2(x.z); fma2(aAL[i], xb, w2.x); fma2(aAH[i], xb, w2.y);
                            xb = bcast2(x.w); fma2(aAL[i], xb, w3.x); fma2(aAH[i], xb, w3.y);
                        }
                        if (okB) {
                            const float4 x = *(const float4*)(inB + (size_t)ix * 32 + c4);
                            u64 xb;
                            xb = bcast2(x.x); fma2(aBL[i], xb, w0.x); fma2(aBH[i], xb, w0.y);
                            xb = bcast2(x.y); fma2(aBL[i], xb, w1.x); fma2(aBH[i], xb, w1.y);
                            xb = bcast2(x.z); fma2(aBL[i], xb, w2.x); fma2(aBH[i], xb, w2.y);
                            xb = bcast2(x.w); fma2(aBL[i], xb, w3.x); fma2(aBH[i], xb, w3.y);
                        }
                    }
                }
            }
        }
    }
    float* outA = out + ((size_t)(n * OH + oyA) * OW) * 32 + co0;
#pragma unroll
    for (int i = 0; i < TOX; i++) {
        if (ox0 + i < OW) {
            const float2 lo = unpack2(aAL[i]), hi = unpack2(aAH[i]);
            float4 v;
            v.x = elu_(lo.x); v.y = elu_(lo.y); v.z = elu_(hi.x); v.w = elu_(hi.y);
            *(float4*)(outA + (size_t)(ox0 + i) * 32) = v;
        }
    }
    if (hasB) {
        float* outB = out + ((size_t)(n * OH + oyA + 1) * OW) * 32 + co0;
#pragma unroll
        for (int i = 0; i < TOX; i++) {
            if (ox0 + i < OW) {
                const float2 lo = unpack2(aBL[i]), hi = unpack2(aBH[i]);
                float4 v;
                v.x = elu_(lo.x); v.y = elu_(lo.y); v.z = elu_(hi.x); v.w = elu_(hi.y);
                *(float4*)(outB + (size_t)(ox0 + i) * 32) = v;
            }
        }
    }
}

// ---------------------------------------------------------------------------
// convN v3 (single-row, BLK templated) — conv3 (R12 best) + conv4 (R8 best)
// ---------------------------------------------------------------------------
template <int IH, int IW, int OH, int OW, int PAD, int TOX, int OXT, int ROWS,
          int IPB, int BLK>
__global__ void __launch_bounds__(8 * OXT * ROWS * IPB, BLK)
conv32_v3(const float* __restrict__ in, const float* __restrict__ w,
          const float* __restrict__ bias, float* __restrict__ out)
{
    __shared__ __align__(16) float sw[9 * 32 * 32];
    const int tid = threadIdx.x;
    const int NTH = 8 * OXT * ROWS * IPB;
    for (int i = tid * 4; i < 9 * 32 * 32; i += NTH * 4)
        *(float4*)(sw + i) = *(const float4*)(w + i);
    __syncthreads();

    const int cg  = tid & 7;
    int rest      = tid >> 3;
    const int oxg = rest % OXT;  rest /= OXT;
    const int ry  = rest % ROWS;
    const int img = rest / ROWS;
    const int co0 = cg * 4;
    const int ox0 = oxg * TOX;
    const int oy  = blockIdx.x * ROWS + ry;
    const int n   = blockIdx.y * IPB + img;
    if (oy >= OH) return;

    u64 aL[TOX], aH[TOX];
    const u64 bL = pack2(bias[co0],     bias[co0 + 1]);
    const u64 bH = pack2(bias[co0 + 2], bias[co0 + 3]);
#pragma unroll
    for (int i = 0; i < TOX; i++) { aL[i] = bL; aH[i] = bH; }

#pragma unroll 1
    for (int ky = 0; ky < 3; ky++) {
        const int iy = oy * 2 + ky - PAD;
        if (iy < 0 || iy >= IH) continue;
        const float* inr = in + ((size_t)(n * IH + iy) * IW) * 32;
#pragma unroll
        for (int kx = 0; kx < 3; kx++) {
            const float* swk = sw + ((ky * 3 + kx) * 32) * 32 + co0;
#pragma unroll
            for (int c4 = 0; c4 < 32; c4 += 4) {
                const ulonglong2 w0 = *(const ulonglong2*)(swk + (c4 + 0) * 32);
                const ulonglong2 w1 = *(const ulonglong2*)(swk + (c4 + 1) * 32);
                const ulonglong2 w2 = *(const ulonglong2*)(swk + (c4 + 2) * 32);
                const ulonglong2 w3 = *(const ulonglong2*)(swk + (c4 + 3) * 32);
#pragma unroll
                for (int i = 0; i < TOX; i++) {
                    const int ix = (ox0 + i) * 2 + kx - PAD;
                    if (ix >= 0 && ix < IW) {
                        const float4 x = *(const float4*)(inr + (size_t)ix * 32 + c4);
                        u64 xb;
                        xb = bcast2(x.x); fma2(aL[i], xb, w0.x); fma2(aH[i], xb, w0.y);
                        xb = bcast2(x.y); fma2(aL[i], xb, w1.x); fma2(aH[i], xb, w1.y);
                        xb = bcast2(x.z); fma2(aL[i], xb, w2.x); fma2(aH[i], xb, w2.y);
                        xb = bcast2(x.w); fma2(aL[i], xb, w3.x); fma2(aH[i], xb, w3.y);
                    }
                }
            }
        }
    }
    float* outr = out + ((size_t)(n * OH + oy) * OW) * 32 + co0;
#pragma unroll
    for (int i = 0; i < TOX; i++) {
        if (ox0 + i < OW) {
            const float2 lo = unpack2(aL[i]), hi = unpack2(aH[i]);
            float4 v;
            v.x = elu_(lo.x); v.y = elu_(lo.y); v.z = elu_(hi.x); v.w = elu_(hi.y);
            *(float4*)(outr + (size_t)(ox0 + i) * 32) = v;
        }
    }
}

// ---------------------------------------------------------------------------
// SGEMM (unchanged)
// ---------------------------------------------------------------------------
__global__ void __launch_bounds__(256, 2)
sgemm_xg_v2(const float* __restrict__ A, const float* __restrict__ B,
            const float* __restrict__ bias, float* __restrict__ C)
{
    __shared__ __align__(16) float As[8][128];
    __shared__ __align__(16) float Bs[8][128];
    const int bx  = blockIdx.x;
    const int by  = blockIdx.y;
    const int tid = threadIdx.x;
    const int tr  = (tid / 16) * 8;
    const int tc  = (tid % 16) * 8;

    u64 acc[8][4];
#pragma unroll
    for (int i = 0; i < 8; i++)
#pragma unroll
        for (int j = 0; j < 4; j++) acc[i][j] = 0ull;

    const int ar = tid >> 1,  ac = (tid & 1) * 4;
    const int br = tid >> 5,  bc = (tid & 31) * 4;
    const float* Aptr = A + (size_t)(by * 128 + ar) * FEAT + ac;
    const float* Bptr = B + (size_t)br * 1024 + bx * 128 + bc;

    for (int k0 = 0; k0 < FEAT; k0 += 8) {
        const float4 av = *(const float4*)(Aptr + k0);
        As[ac + 0][ar] = av.x; As[ac + 1][ar] = av.y;
        As[ac + 2][ar] = av.z; As[ac + 3][ar] = av.w;
        *(float4*)&Bs[br][bc] = *(const float4*)(Bptr + (size_t)k0 * 1024);
        __syncthreads();
#pragma unroll
        for (int kk = 0; kk < 8; kk++) {
            const float4 a0 = *(const float4*)&As[kk][tr];
            const float4 a1 = *(const float4*)&As[kk][tr + 4];
            const ulonglong2 b0 = *(const ulonglong2*)&Bs[kk][tc];
            const ulonglong2 b1 = *(const ulonglong2*)&Bs[kk][tc + 4];
            const float a[8] = {a0.x, a0.y, a0.z, a0.w, a1.x, a1.y, a1.z, a1.w};
#pragma unroll
            for (int i = 0; i < 8; i++) {
                const u64 ab = bcast2(a[i]);
                fma2(acc[i][0], ab, b0.x);
                fma2(acc[i][1], ab, b0.y);
                fma2(acc[i][2], ab, b1.x);
                fma2(acc[i][3], ab, b1.y);
            }
        }
        __syncthreads();
    }

#pragma unroll
    for (int i = 0; i < 8; i++) {
        const int row = by * 128 + tr + i;
        float* crow = C + (size_t)row * 1024 + bx * 128 + tc;
#pragma unroll
        for (int j = 0; j < 2; j++) {
            const float2 p0 = unpack2(acc[i][j * 2 + 0]);
            const float2 p1 = unpack2(acc[i][j * 2 + 1]);
            float4 v;
            v.x = p0.x + bias[bx * 128 + tc + j * 4 + 0];
            v.y = p0.y + bias[bx * 128 + tc + j * 4 + 1];
            v.z = p1.x + bias[bx * 128 + tc + j * 4 + 2];
            v.w = p1.y + bias[bx * 128 + tc + j * 4 + 3];
            *(float4*)(crow + j * 4) = v;
        }
    }
}

// ---------------------------------------------------------------------------
// LSTM v6: 2-CTA cluster per trajectory + split-k within each CTA.
// 256 threads/CTA: half h = tid>>7 accumulates k2 in [64h, 64h+64); partials
// are combined through smem. Doubles warps/SM (4 -> 8) at identical weight
// traffic, doubling in-flight LDG bytes (the R15 latency limiter).
// ---------------------------------------------------------------------------
__device__ __forceinline__ float sigmoidf_(float x) { return 1.f / (1.f + expf(-x)); }

__global__ void __launch_bounds__(256) __cluster_dims__(2, 1, 1)
lstm_cluster_v6(const float* __restrict__ xg,
                const ulonglong2* __restrict__ wij,
                const ulonglong2* __restrict__ wfo,
                const float* __restrict__ fcw, const float* __restrict__ fcb,
                const float* __restrict__ c0, const float* __restrict__ h0,
                float* __restrict__ out)
{
    const int n    = blockIdx.x >> 1;     // trajectory
    const int tid  = threadIdx.x;         // 0..255
    const int lt   = tid & 127;           // local hidden index within CTA half
    const int half = tid >> 7;            // k-split half
    uint32_t rank;
    asm("mov.u32 %0, %%cluster_ctarank;" : "=r"(rank));
    const int tg = (int)rank * 128 + lt;  // global hidden index

    __shared__ __align__(16) float sh[2][HID];
    __shared__ __align__(16) float4 spart[128];

    float c = 0.f;
    if (half == 0) c = c0[(size_t)n * HID + tg];
    if (half == 0) {
        sh[0][lt]       = h0[(size_t)n * HID + lt];
        sh[0][128 + lt] = h0[(size_t)n * HID + 128 + lt];
    }
    __syncthreads();
    asm volatile("barrier.cluster.arrive.aligned;" ::: "memory");
    asm volatile("barrier.cluster.wait.aligned;" ::: "memory");

    const uint32_t peer = rank ^ 1u;
    const int wrp = tid >> 5, lane = tid & 31;
    const int k2lo = half * 64;

    for (int t = 0; t < TL; t++) {
        const int p = t & 1, q = p ^ 1;
        const float* xrow = xg + (size_t)(n * TL + t) * 1024;
        u64 ai = 0ull, aj = 0ull, af = 0ull, ao = 0ull;
        if (half == 0) {
            ai = pack2(xrow[tg],       0.f);
            aj = pack2(xrow[256 + tg], 0.f);
            af = pack2(xrow[512 + tg], 0.f);
            ao = pack2(xrow[768 + tg], 0.f);
        }

#pragma unroll 4
        for (int k2i = 0; k2i < 64; k2i++) {
            const int k2 = k2lo + k2i;
            const u64 h2 = *(const u64*)(&sh[p][2 * k2]);
            const ulonglong2 w01 = wij[(size_t)k2 * 256 + tg];
            const ulonglong2 w23 = wfo[(size_t)k2 * 256 + tg];
            fma2(ai, h2, w01.x);
            fma2(aj, h2, w01.y);
            fma2(af, h2, w23.x);
            fma2(ao, h2, w23.y);
        }
        // upper half publishes its 4 partial gate sums
        if (half == 1) {
            float4 pv;
            pv.x = sum2(ai); pv.y = sum2(aj); pv.z = sum2(af); pv.w = sum2(ao);
            spart[lt] = pv;
        }
        __syncthreads();

        if (half == 0) {
            const float4 pv = spart[lt];
            const float gi = sum2(ai) + pv.x, gj = sum2(aj) + pv.y;
            const float gf = sum2(af) + pv.z, go = sum2(ao) + pv.w;

            const float nc = c * sigmoidf_(gf + 1.f) + sigmoidf_(gi) * tanhf(gj);
            const float nh = tanhf(nc) * sigmoidf_(go);
            c = nc;

            sh[q][tg] = nh;
            uint32_t laddr = (uint32_t)__cvta_generic_to_shared(&sh[q][tg]);
            uint32_t raddr;
            asm("mapa.shared::cluster.u32 %0, %1, %2;"
                : "=r"(raddr) : "r"(laddr), "r"(peer));
            asm volatile("st.shared::cluster.f32 [%0], %1;"
                         :: "r"(raddr), "f"(nh) : "memory");
        }
        asm volatile("barrier.cluster.arrive.aligned;" ::: "memory");
        asm volatile("barrier.cluster.wait.aligned;" ::: "memory");

        // FC head: CTA rank r covers cols [9r, 9r+9); warps 0..2, 3 cols each
        if (wrp < 3) {
#pragma unroll
            for (int cc = 0; cc < 3; cc++) {
                const int col = (int)rank * 9 + wrp * 3 + cc;
                float s = 0.f;
#pragma unroll
                for (int k = lane; k < HID; k += 32) s += sh[q][k] * fcw[(size_t)k * NOUT + col];
#pragma unroll
                for (int off = 16; off; off >>= 1) s += __shfl_down_sync(0xffffffffu, s, off);
                if (lane == 0)
                    out[(size_t)(n * TL + t) * NOUT + col] = s + fcb[col];
            }
        }
    }
}

// ---------------------------------------------------------------------------
// Launch
// ---------------------------------------------------------------------------
extern "C" void kernel_launch(void* const* d_in, const int* in_sizes, int n_in,
                              void* d_out, int out_size)
{
    (void)in_sizes; (void)n_in; (void)out_size;
    const float* inp = (const float*)d_in[0];
    const float* w1  = (const float*)d_in[1];
    const float* b1  = (const float*)d_in[2];
    const float* w2  = (const float*)d_in[3];
    const float* b2  = (const float*)d_in[4];
    const float* w3  = (const float*)d_in[5];
    const float* b3  = (const float*)d_in[6];
    const float* w4  = (const float*)d_in[7];
    const float* b4  = (const float*)d_in[8];
    const float* lw  = (const float*)d_in[9];
    const float* lb  = (const float*)d_in[10];
    const float* fw  = (const float*)d_in[11];
    const float* fb  = (const float*)d_in[12];
    const float* c0  = (const float*)d_in[13];
    const float* h0  = (const float*)d_in[14];
    float* out = (float*)d_out;

    float *c1, *c2, *c3, *c4, *xg;
    ulonglong2 *wij, *wfo;
    cudaGetSymbolAddress((void**)&c1,  g_c1);
    cudaGetSymbolAddress((void**)&c2,  g_c2);
    cudaGetSymbolAddress((void**)&c3,  g_c3);
    cudaGetSymbolAddress((void**)&c4,  g_c4);
    cudaGetSymbolAddress((void**)&xg,  g_xg);
    cudaGetSymbolAddress((void**)&wij, g_wij);
    cudaGetSymbolAddress((void**)&wfo, g_wfo);

    reorder_wh3_k<<<128, 256>>>(lw, wij, wfo);

    // conv stack — per-layer measured-best configs (R15):
    conv1_v5<<<dim3(11, NIMG), 352>>>(inp, w1, b1, c1);
    conv32_v6<42, 42, 21, 21, 0, 3, 7, 4><<<dim3(3, NIMG), 224>>>(c1, w2, b2, c2);
    conv32_v3<21, 21, 11, 11, 1, 3, 4, 6, 1, 3><<<dim3(2, NIMG), 192>>>(c2, w3, b3, c3);
    conv32_v3<11, 11,  6,  6, 1, 6, 1, 6, 4, 2><<<dim3(1, NIMG / 4), 192>>>(c3, w4, b4, c4);

    sgemm_xg_v2<<<dim3(8, 16), 256>>>(c4, lw, lb, xg);

    // recurrence + FC: 2-CTA cluster per trajectory, split-k (8 warps/SM)
    lstm_cluster_v6<<<NT * 2, 256>>>(xg, wij, wfo, fw, fb, c0, h0, out);
}

// round 17
// speedup vs baseline: 1.8820x; 1.1656x over previous
#include <cuda_runtime.h>
#include <math.h>
#include <stdint.h>
#include <string.h>

// ---------------------------------------------------------------------------
// Problem constants
// ---------------------------------------------------------------------------
#define NIMG   2048
#define NT     32
#define TL     64
#define FEAT   1152
#define HID    256
#define NOUT   18

typedef unsigned long long u64;

// ---------------- packed f32x2 helpers (FFMA2: PTX-only pattern) -----------
__device__ __forceinline__ u64 bcast2(float x) {
    u64 d; asm("mov.b64 %0, {%1, %1};" : "=l"(d) : "f"(x)); return d;
}
__device__ __forceinline__ u64 pack2(float a, float b) {
    u64 d; asm("mov.b64 %0, {%1, %2};" : "=l"(d) : "f"(a), "f"(b)); return d;
}
__device__ __forceinline__ float2 unpack2(u64 v) {
    float2 r; asm("mov.b64 {%0, %1}, %2;" : "=f"(r.x), "=f"(r.y) : "l"(v)); return r;
}
__device__ __forceinline__ void fma2(u64& d, u64 a, u64 b) {
    asm("fma.rn.f32x2 %0, %1, %2, %0;" : "+l"(d) : "l"(a), "l"(b));
}
__device__ __forceinline__ float sum2(u64 v) {
    float2 r = unpack2(v); return r.x + r.y;
}

__device__ __forceinline__ float elu_(float v) { return v > 0.f ? v : (__expf(v) - 1.f); }

// ------------------------- device scratch (no cudaMalloc allowed) ----------
__device__ float g_c1[(size_t)NIMG * 42 * 42 * 32];   // 462 MB
__device__ float g_c2[(size_t)NIMG * 21 * 21 * 32];   // 116 MB
__device__ float g_c3[(size_t)NIMG * 11 * 11 * 32];   //  32 MB
__device__ float g_c4[(size_t)NIMG * 6 * 6 * 32];     //   9 MB
__device__ float g_xg[(size_t)NIMG * 1024];           //   8 MB  x@Wx + b
__device__ ulonglong2 g_wij[128 * HID];               // 512 KB (i,j) k-pairs
__device__ ulonglong2 g_wfo[128 * HID];               // 512 KB (f,o) k-pairs

// ---------------------------------------------------------------------------
// Wh reorder, split coalesced layout (R14, measured-good)
// ---------------------------------------------------------------------------
__global__ void reorder_wh3_k(const float* __restrict__ lw,
                              ulonglong2* __restrict__ wij,
                              ulonglong2* __restrict__ wfo)
{
    const int k2 = blockIdx.x;    // 0..127
    const int t  = threadIdx.x;   // 0..255
    const float* r0 = lw + (size_t)(FEAT + 2 * k2) * 1024;
    const float* r1 = lw + (size_t)(FEAT + 2 * k2 + 1) * 1024;
    ulonglong2 vij, vfo;
    vij.x = pack2(r0[t],       r1[t]);
    vij.y = pack2(r0[256 + t], r1[256 + t]);
    vfo.x = pack2(r0[512 + t], r1[512 + t]);
    vfo.y = pack2(r0[768 + t], r1[768 + t]);
    wij[(size_t)k2 * 256 + t] = vij;
    wfo[(size_t)k2 * 256 + t] = vfo;
}

// ---------------------------------------------------------------------------
// conv1 v5 (ci-pair, R15/R16 measured-good): Cin=4 -> Cout=32, 84x84 -> 42x42.
// ---------------------------------------------------------------------------
__global__ void __launch_bounds__(352, 2)
conv1_v5(const float* __restrict__ in, const float* __restrict__ w,
         const float* __restrict__ bias, float* __restrict__ out)
{
    __shared__ __align__(16) u64 sw2[9 * 2 * 32];     // [kpos][p][co] pairs
    const int tid = threadIdx.x;
    for (int i = tid; i < 9 * 2 * 32; i += 352) {
        const int kpos = i >> 6, p = (i >> 5) & 1, co = i & 31;
        sw2[i] = pack2(w[(kpos * 4 + 2 * p) * 32 + co],
                       w[(kpos * 4 + 2 * p + 1) * 32 + co]);
    }
    __syncthreads();

    const int cg   = tid & 7;
    const int rest = tid >> 3;
    const int oxg  = rest % 11;
    const int ry   = rest / 11;
    const int oy   = blockIdx.x * 4 + ry;
    const int n    = blockIdx.y;
    const int co0  = cg * 4;
    const int ox0  = oxg * 4;
    if (oy >= 42) return;

    u64 acc[4][4];
#pragma unroll
    for (int i = 0; i < 4; i++)
#pragma unroll
        for (int c = 0; c < 4; c++) acc[i][c] = 0ull;

#pragma unroll 1
    for (int ky = 0; ky < 3; ky++) {
        const int iy = oy * 2 + ky;
        if (iy >= 84) continue;
        const float* inr = in + ((size_t)(n * 84 + iy) * 84) * 4;
#pragma unroll
        for (int kx = 0; kx < 3; kx++) {
            const u64* swk = sw2 + (ky * 3 + kx) * 2 * 32;
            const ulonglong2 wa01 = *(const ulonglong2*)(swk + co0);
            const ulonglong2 wa23 = *(const ulonglong2*)(swk + co0 + 2);
            const ulonglong2 wb01 = *(const ulonglong2*)(swk + 32 + co0);
            const ulonglong2 wb23 = *(const ulonglong2*)(swk + 32 + co0 + 2);
#pragma unroll
            for (int i = 0; i < 4; i++) {
                const int ix = (ox0 + i) * 2 + kx;
                if (ix < 84) {
                    const ulonglong2 xv = *(const ulonglong2*)(inr + (size_t)ix * 4);
                    fma2(acc[i][0], xv.x, wa01.x);
                    fma2(acc[i][1], xv.x, wa01.y);
                    fma2(acc[i][2], xv.x, wa23.x);
                    fma2(acc[i][3], xv.x, wa23.y);
                    fma2(acc[i][0], xv.y, wb01.x);
                    fma2(acc[i][1], xv.y, wb01.y);
                    fma2(acc[i][2], xv.y, wb23.x);
                    fma2(acc[i][3], xv.y, wb23.y);
                }
            }
        }
    }
    const float4 bv = *(const float4*)(bias + co0);
    float* outr = out + ((size_t)(n * 42 + oy) * 42) * 32 + co0;
#pragma unroll
    for (int i = 0; i < 4; i++) {
        const int ox = ox0 + i;
        if (ox < 42) {
            float4 v;
            v.x = elu_(sum2(acc[i][0]) + bv.x);
            v.y = elu_(sum2(acc[i][1]) + bv.y);
            v.z = elu_(sum2(acc[i][2]) + bv.z);
            v.w = elu_(sum2(acc[i][3]) + bv.w);
            *(float4*)(outr + (size_t)ox * 32) = v;
        }
    }
}

// ---------------------------------------------------------------------------
// convN v6 (TOY=2, for conv2 — R13/R16 measured-good)
// ---------------------------------------------------------------------------
template <int IH, int IW, int OH, int OW, int PAD, int TOX, int OXT, int RP>
__global__ void __launch_bounds__(8 * OXT * RP, 2)
conv32_v6(const float* __restrict__ in, const float* __restrict__ w,
          const float* __restrict__ bias, float* __restrict__ out)
{
    __shared__ __align__(16) float sw[9 * 32 * 32];
    const int tid = threadIdx.x;
    const int NTH = 8 * OXT * RP;
    for (int i = tid * 4; i < 9 * 32 * 32; i += NTH * 4)
        *(float4*)(sw + i) = *(const float4*)(w + i);
    __syncthreads();

    const int cg   = tid & 7;
    int rest       = tid >> 3;
    const int oxg  = rest % OXT;
    const int rp   = rest / OXT;
    const int pair = blockIdx.x * RP + rp;
    const int oyA  = 2 * pair;
    const int n    = blockIdx.y;
    const int co0  = cg * 4;
    const int ox0  = oxg * TOX;
    if (oyA >= OH) return;
    const bool hasB = (oyA + 1) < OH;

    u64 aAL[TOX], aAH[TOX], aBL[TOX], aBH[TOX];
    const u64 bL = pack2(bias[co0],     bias[co0 + 1]);
    const u64 bH = pack2(bias[co0 + 2], bias[co0 + 3]);
#pragma unroll
    for (int i = 0; i < TOX; i++) { aAL[i] = bL; aAH[i] = bH; aBL[i] = bL; aBH[i] = bH; }

#pragma unroll 1
    for (int ky = 0; ky < 3; ky++) {
        const int iyA = oyA * 2 + ky - PAD;
        const int iyB = iyA + 2;
        const bool okA = (iyA >= 0) && (iyA < IH);
        const bool okB = hasB && (iyB < IH);
        if (!okA && !okB) continue;
        const float* inA = in + ((size_t)(n * IH + iyA) * IW) * 32;
        const float* inB = in + ((size_t)(n * IH + iyB) * IW) * 32;
#pragma unroll
        for (int kx = 0; kx < 3; kx++) {
            const float* swk = sw + ((ky * 3 + kx) * 32) * 32 + co0;
#pragma unroll
            for (int c4 = 0; c4 < 32; c4 += 4) {
                const ulonglong2 w0 = *(const ulonglong2*)(swk + (c4 + 0) * 32);
                const ulonglong2 w1 = *(const ulonglong2*)(swk + (c4 + 1) * 32);
                const ulonglong2 w2 = *(const ulonglong2*)(swk + (c4 + 2) * 32);
                const ulonglong2 w3 = *(const ulonglong2*)(swk + (c4 + 3) * 32);
#pragma unroll
                for (int i = 0; i < TOX; i++) {
                    const int ix = (ox0 + i) * 2 + kx - PAD;
                    if (ix >= 0 && ix < IW) {
                        if (okA) {
                            const float4 x = *(const float4*)(inA + (size_t)ix * 32 + c4);
                            u64 xb;
                            xb = bcast2(x.x); fma2(aAL[i], xb, w0.x); fma2(aAH[i], xb, w0.y);
                            xb = bcast2(x.y); fma2(aAL[i], xb, w1.x); fma2(aAH[i], xb, w1.y);
                            xb = bcast2(x.z); fma2(aAL[i], xb, w2.x); fma2(aAH[i], xb, w2.y);
                            xb = bcast2(x.w); fma2(aAL[i], xb, w3.x); fma2(aAH[i], xb, w3.y);
                        }
                        if (okB) {
                            const float4 x = *(const float4*)(inB + (size_t)ix * 32 + c4);
                            u64 xb;
                            xb = bcast2(x.x); fma2(aBL[i], xb, w0.x); fma2(aBH[i], xb, w0.y);
                            xb = bcast2(x.y); fma2(aBL[i], xb, w1.x); fma2(aBH[i], xb, w1.y);
                            xb = bcast2(x.z); fma2(aBL[i], xb, w2.x); fma2(aBH[i], xb, w2.y);
                            xb = bcast2(x.w); fma2(aBL[i], xb, w3.x); fma2(aBH[i], xb, w3.y);
                        }
                    }
                }
            }
        }
    }
    float* outA = out + ((size_t)(n * OH + oyA) * OW) * 32 + co0;
#pragma unroll
    for (int i = 0; i < TOX; i++) {
        if (ox0 + i < OW) {
            const float2 lo = unpack2(aAL[i]), hi = unpack2(aAH[i]);
            float4 v;
            v.x = elu_(lo.x); v.y = elu_(lo.y); v.z = elu_(hi.x); v.w = elu_(hi.y);
            *(float4*)(outA + (size_t)(ox0 + i) * 32) = v;
        }
    }
    if (hasB) {
        float* outB = out + ((size_t)(n * OH + oyA + 1) * OW) * 32 + co0;
#pragma unroll
        for (int i = 0; i < TOX; i++) {
            if (ox0 + i < OW) {
                const float2 lo = unpack2(aBL[i]), hi = unpack2(aBH[i]);
                float4 v;
                v.x = elu_(lo.x); v.y = elu_(lo.y); v.z = elu_(hi.x); v.w = elu_(hi.y);
                *(float4*)(outB + (size_t)(ox0 + i) * 32) = v;
            }
        }
    }
}

// ---------------------------------------------------------------------------
// convN v3 (single-row, BLK templated) — conv3 (R12 best) + conv4 (R8 best)
// ---------------------------------------------------------------------------
template <int IH, int IW, int OH, int OW, int PAD, int TOX, int OXT, int ROWS,
          int IPB, int BLK>
__global__ void __launch_bounds__(8 * OXT * ROWS * IPB, BLK)
conv32_v3(const float* __restrict__ in, const float* __restrict__ w,
          const float* __restrict__ bias, float* __restrict__ out)
{
    __shared__ __align__(16) float sw[9 * 32 * 32];
    const int tid = threadIdx.x;
    const int NTH = 8 * OXT * ROWS * IPB;
    for (int i = tid * 4; i < 9 * 32 * 32; i += NTH * 4)
        *(float4*)(sw + i) = *(const float4*)(w + i);
    __syncthreads();

    const int cg  = tid & 7;
    int rest      = tid >> 3;
    const int oxg = rest % OXT;  rest /= OXT;
    const int ry  = rest % ROWS;
    const int img = rest / ROWS;
    const int co0 = cg * 4;
    const int ox0 = oxg * TOX;
    const int oy  = blockIdx.x * ROWS + ry;
    const int n   = blockIdx.y * IPB + img;
    if (oy >= OH) return;

    u64 aL[TOX], aH[TOX];
    const u64 bL = pack2(bias[co0],     bias[co0 + 1]);
    const u64 bH = pack2(bias[co0 + 2], bias[co0 + 3]);
#pragma unroll
    for (int i = 0; i < TOX; i++) { aL[i] = bL; aH[i] = bH; }

#pragma unroll 1
    for (int ky = 0; ky < 3; ky++) {
        const int iy = oy * 2 + ky - PAD;
        if (iy < 0 || iy >= IH) continue;
        const float* inr = in + ((size_t)(n * IH + iy) * IW) * 32;
#pragma unroll
        for (int kx = 0; kx < 3; kx++) {
            const float* swk = sw + ((ky * 3 + kx) * 32) * 32 + co0;
#pragma unroll
            for (int c4 = 0; c4 < 32; c4 += 4) {
                const ulonglong2 w0 = *(const ulonglong2*)(swk + (c4 + 0) * 32);
                const ulonglong2 w1 = *(const ulonglong2*)(swk + (c4 + 1) * 32);
                const ulonglong2 w2 = *(const ulonglong2*)(swk + (c4 + 2) * 32);
                const ulonglong2 w3 = *(const ulonglong2*)(swk + (c4 + 3) * 32);
#pragma unroll
                for (int i = 0; i < TOX; i++) {
                    const int ix = (ox0 + i) * 2 + kx - PAD;
                    if (ix >= 0 && ix < IW) {
                        const float4 x = *(const float4*)(inr + (size_t)ix * 32 + c4);
                        u64 xb;
                        xb = bcast2(x.x); fma2(aL[i], xb, w0.x); fma2(aH[i], xb, w0.y);
                        xb = bcast2(x.y); fma2(aL[i], xb, w1.x); fma2(aH[i], xb, w1.y);
                        xb = bcast2(x.z); fma2(aL[i], xb, w2.x); fma2(aH[i], xb, w2.y);
                        xb = bcast2(x.w); fma2(aL[i], xb, w3.x); fma2(aH[i], xb, w3.y);
                    }
                }
            }
        }
    }
    float* outr = out + ((size_t)(n * OH + oy) * OW) * 32 + co0;
#pragma unroll
    for (int i = 0; i < TOX; i++) {
        if (ox0 + i < OW) {
            const float2 lo = unpack2(aL[i]), hi = unpack2(aH[i]);
            float4 v;
            v.x = elu_(lo.x); v.y = elu_(lo.y); v.z = elu_(hi.x); v.w = elu_(hi.y);
            *(float4*)(outr + (size_t)(ox0 + i) * 32) = v;
        }
    }
}

// ---------------------------------------------------------------------------
// SGEMM v3: double-buffered smem. One __syncthreads per k-tile (vs two) and
// next-tile LDGs overlap the 32-fma2 burst of the current tile.
// ---------------------------------------------------------------------------
__global__ void __launch_bounds__(256, 2)
sgemm_xg_v3(const float* __restrict__ A, const float* __restrict__ B,
            const float* __restrict__ bias, float* __restrict__ C)
{
    __shared__ __align__(16) float As[2][8][128];
    __shared__ __align__(16) float Bs[2][8][128];
    const int bx  = blockIdx.x;
    const int by  = blockIdx.y;
    const int tid = threadIdx.x;
    const int tr  = (tid / 16) * 8;
    const int tc  = (tid % 16) * 8;

    u64 acc[8][4];
#pragma unroll
    for (int i = 0; i < 8; i++)
#pragma unroll
        for (int j = 0; j < 4; j++) acc[i][j] = 0ull;

    const int ar = tid >> 1,  ac = (tid & 1) * 4;
    const int br = tid >> 5,  bc = (tid & 31) * 4;
    const float* Aptr = A + (size_t)(by * 128 + ar) * FEAT + ac;
    const float* Bptr = B + (size_t)br * 1024 + bx * 128 + bc;

    // preload tile 0
    {
        const float4 av = *(const float4*)(Aptr);
        As[0][ac + 0][ar] = av.x; As[0][ac + 1][ar] = av.y;
        As[0][ac + 2][ar] = av.z; As[0][ac + 3][ar] = av.w;
        *(float4*)&Bs[0][br][bc] = *(const float4*)(Bptr);
    }
    __syncthreads();

    int buf = 0;
    for (int k0 = 0; k0 < FEAT; k0 += 8) {
        const bool more = (k0 + 8) < FEAT;
        float4 av2, bv2;
        if (more) {
            av2 = *(const float4*)(Aptr + k0 + 8);
            bv2 = *(const float4*)(Bptr + (size_t)(k0 + 8) * 1024);
        }
#pragma unroll
        for (int kk = 0; kk < 8; kk++) {
            const float4 a0 = *(const float4*)&As[buf][kk][tr];
            const float4 a1 = *(const float4*)&As[buf][kk][tr + 4];
            const ulonglong2 b0 = *(const ulonglong2*)&Bs[buf][kk][tc];
            const ulonglong2 b1 = *(const ulonglong2*)&Bs[buf][kk][tc + 4];
            const float a[8] = {a0.x, a0.y, a0.z, a0.w, a1.x, a1.y, a1.z, a1.w};
#pragma unroll
            for (int i = 0; i < 8; i++) {
                const u64 ab = bcast2(a[i]);
                fma2(acc[i][0], ab, b0.x);
                fma2(acc[i][1], ab, b0.y);
                fma2(acc[i][2], ab, b1.x);
                fma2(acc[i][3], ab, b1.y);
            }
        }
        if (more) {
            const int nb = buf ^ 1;
            As[nb][ac + 0][ar] = av2.x; As[nb][ac + 1][ar] = av2.y;
            As[nb][ac + 2][ar] = av2.z; As[nb][ac + 3][ar] = av2.w;
            *(float4*)&Bs[nb][br][bc] = bv2;
            __syncthreads();
            buf = nb;
        }
    }

#pragma unroll
    for (int i = 0; i < 8; i++) {
        const int row = by * 128 + tr + i;
        float* crow = C + (size_t)row * 1024 + bx * 128 + tc;
#pragma unroll
        for (int j = 0; j < 2; j++) {
            const float2 p0 = unpack2(acc[i][j * 2 + 0]);
            const float2 p1 = unpack2(acc[i][j * 2 + 1]);
            float4 v;
            v.x = p0.x + bias[bx * 128 + tc + j * 4 + 0];
            v.y = p0.y + bias[bx * 128 + tc + j * 4 + 1];
            v.z = p1.x + bias[bx * 128 + tc + j * 4 + 2];
            v.w = p1.y + bias[bx * 128 + tc + j * 4 + 3];
            *(float4*)(crow + j * 4) = v;
        }
    }
}

// ---------------------------------------------------------------------------
// LSTM v7: 4-CTA cluster per trajectory (rank owns hidden [64r,64r+64)) with
// ksplit-4 (quarter q covers k2 in [32q,32q+32)). Per-SM weight traffic
// 0.25 MB/step at 8 warps/SM. h broadcast: 3 DSMEM stores + 1 cluster
// barrier per step; gate partials combined through smem.
// ---------------------------------------------------------------------------
__device__ __forceinline__ float sigmoidf_(float x) { return 1.f / (1.f + expf(-x)); }

__global__ void __launch_bounds__(256) __cluster_dims__(4, 1, 1)
lstm_cluster_v7(const float* __restrict__ xg,
                const ulonglong2* __restrict__ wij,
                const ulonglong2* __restrict__ wfo,
                const float* __restrict__ fcw, const float* __restrict__ fcb,
                const float* __restrict__ c0, const float* __restrict__ h0,
                float* __restrict__ out)
{
    const int n    = blockIdx.x >> 2;     // trajectory
    const int tid  = threadIdx.x;         // 0..255
    const int lt   = tid & 63;            // local hidden index within CTA
    const int quar = tid >> 6;            // k-split quarter
    uint32_t rank;
    asm("mov.u32 %0, %%cluster_ctarank;" : "=r"(rank));
    const int tg = (int)rank * 64 + lt;   // global hidden index

    __shared__ __align__(16) float  sh[2][HID];
    __shared__ __align__(16) float4 spart[3][64];

    float c = 0.f;
    if (quar == 0) c = c0[(size_t)n * HID + tg];
    sh[0][tid] = h0[(size_t)n * HID + tid];
    __syncthreads();
    asm volatile("barrier.cluster.arrive.aligned;" ::: "memory");
    asm volatile("barrier.cluster.wait.aligned;" ::: "memory");

    const int wrp = tid >> 5, lane = tid & 31;
    const int k2lo = quar * 32;

    for (int t = 0; t < TL; t++) {
        const int p = t & 1, q = p ^ 1;
        const float* xrow = xg + (size_t)(n * TL + t) * 1024;
        u64 ai = 0ull, aj = 0ull, af = 0ull, ao = 0ull;
        if (quar == 0) {
            ai = pack2(xrow[tg],       0.f);
            aj = pack2(xrow[256 + tg], 0.f);
            af = pack2(xrow[512 + tg], 0.f);
            ao = pack2(xrow[768 + tg], 0.f);
        }

#pragma unroll 4
        for (int k2i = 0; k2i < 32; k2i++) {
            const int k2 = k2lo + k2i;
            const u64 h2 = *(const u64*)(&sh[p][2 * k2]);
            const ulonglong2 w01 = wij[(size_t)k2 * 256 + tg];
            const ulonglong2 w23 = wfo[(size_t)k2 * 256 + tg];
            fma2(ai, h2, w01.x);
            fma2(aj, h2, w01.y);
            fma2(af, h2, w23.x);
            fma2(ao, h2, w23.y);
        }
        if (quar != 0) {
            float4 pv;
            pv.x = sum2(ai); pv.y = sum2(aj); pv.z = sum2(af); pv.w = sum2(ao);
            spart[quar - 1][lt] = pv;
        }
        __syncthreads();

        if (quar == 0) {
            const float4 p1 = spart[0][lt];
            const float4 p2 = spart[1][lt];
            const float4 p3 = spart[2][lt];
            const float gi = sum2(ai) + p1.x + p2.x + p3.x;
            const float gj = sum2(aj) + p1.y + p2.y + p3.y;
            const float gf = sum2(af) + p1.z + p2.z + p3.z;
            const float go = sum2(ao) + p1.w + p2.w + p3.w;

            const float nc = c * sigmoidf_(gf + 1.f) + sigmoidf_(gi) * tanhf(gj);
            const float nh = tanhf(nc) * sigmoidf_(go);
            c = nc;

            sh[q][tg] = nh;
            const uint32_t laddr = (uint32_t)__cvta_generic_to_shared(&sh[q][tg]);
#pragma unroll
            for (int pr = 0; pr < 4; pr++) {
                if (pr != (int)rank) {
                    uint32_t raddr;
                    asm("mapa.shared::cluster.u32 %0, %1, %2;"
                        : "=r"(raddr) : "r"(laddr), "r"((uint32_t)pr));
                    asm volatile("st.shared::cluster.f32 [%0], %1;"
                                 :: "r"(raddr), "f"(nh) : "memory");
                }
            }
        }
        asm volatile("barrier.cluster.arrive.aligned;" ::: "memory");
        asm volatile("barrier.cluster.wait.aligned;" ::: "memory");

        // FC head: rank r covers cols [5r, 5r+5) ∩ [0,18); warps 0..4
        if (wrp < 5) {
            const int col = (int)rank * 5 + wrp;
            if (col < NOUT) {
                float s = 0.f;
#pragma unroll
                for (int k = lane; k < HID; k += 32) s += sh[q][k] * fcw[(size_t)k * NOUT + col];
#pragma unroll
                for (int off = 16; off; off >>= 1) s += __shfl_down_sync(0xffffffffu, s, off);
                if (lane == 0)
                    out[(size_t)(n * TL + t) * NOUT + col] = s + fcb[col];
            }
        }
    }
}

// ---------------------------------------------------------------------------
// Launch
// ---------------------------------------------------------------------------
extern "C" void kernel_launch(void* const* d_in, const int* in_sizes, int n_in,
                              void* d_out, int out_size)
{
    (void)in_sizes; (void)n_in; (void)out_size;
    const float* inp = (const float*)d_in[0];
    const float* w1  = (const float*)d_in[1];
    const float* b1  = (const float*)d_in[2];
    const float* w2  = (const float*)d_in[3];
    const float* b2  = (const float*)d_in[4];
    const float* w3  = (const float*)d_in[5];
    const float* b3  = (const float*)d_in[6];
    const float* w4  = (const float*)d_in[7];
    const float* b4  = (const float*)d_in[8];
    const float* lw  = (const float*)d_in[9];
    const float* lb  = (const float*)d_in[10];
    const float* fw  = (const float*)d_in[11];
    const float* fb  = (const float*)d_in[12];
    const float* c0  = (const float*)d_in[13];
    const float* h0  = (const float*)d_in[14];
    float* out = (float*)d_out;

    float *c1, *c2, *c3, *c4, *xg;
    ulonglong2 *wij, *wfo;
    cudaGetSymbolAddress((void**)&c1,  g_c1);
    cudaGetSymbolAddress((void**)&c2,  g_c2);
    cudaGetSymbolAddress((void**)&c3,  g_c3);
    cudaGetSymbolAddress((void**)&c4,  g_c4);
    cudaGetSymbolAddress((void**)&xg,  g_xg);
    cudaGetSymbolAddress((void**)&wij, g_wij);
    cudaGetSymbolAddress((void**)&wfo, g_wfo);

    reorder_wh3_k<<<128, 256>>>(lw, wij, wfo);

    // conv stack — per-layer measured-best configs (R16, unchanged):
    conv1_v5<<<dim3(11, NIMG), 352>>>(inp, w1, b1, c1);
    conv32_v6<42, 42, 21, 21, 0, 3, 7, 4><<<dim3(3, NIMG), 224>>>(c1, w2, b2, c2);
    conv32_v3<21, 21, 11, 11, 1, 3, 4, 6, 1, 3><<<dim3(2, NIMG), 192>>>(c2, w3, b3, c3);
    conv32_v3<11, 11,  6,  6, 1, 6, 1, 6, 4, 2><<<dim3(1, NIMG / 4), 192>>>(c3, w4, b4, c4);

    // x@Wx GEMM, double-buffered
    sgemm_xg_v3<<<dim3(8, 16), 256>>>(c4, lw, lb, xg);

    // recurrence + FC: 4-CTA cluster per trajectory (128 CTAs / 128 SMs)
    lstm_cluster_v7<<<NT * 4, 256>>>(xg, wij, wfo, fw, fb, c0, h0, out);
}